// round 1
// baseline (speedup 1.0000x reference)
#include <cuda_runtime.h>

// Problem constants: S=2048, B=2, E=1024, H=16, HD=64
#define SEQ   2048
#define BATCH 2
#define EMB   1024
#define NHEAD 16
#define HDIM  64
#define MROWS (SEQ*BATCH)     // 4096
#define QKVN  (3*EMB)         // 3072

// Scratch (allocation-free rule: __device__ globals)
__device__ float g_qkv[(size_t)MROWS * QKVN];    // 48 MB: [m][3E]
__device__ float g_attn[(size_t)MROWS * EMB];    // 16 MB: [m][E]

// ---------------------------------------------------------------------------
// SGEMM: C[M,N] = A[M,K] @ W[N,K]^T + bias[N]
// 128x128 tile, BK=16, 256 threads, 8x8 per thread. M,N,K multiples of 128/16.
// ---------------------------------------------------------------------------
__global__ __launch_bounds__(256) void gemm_bias_k(
    const float* __restrict__ A, const float* __restrict__ W,
    const float* __restrict__ bias, float* __restrict__ C,
    int M, int N, int K)
{
    __shared__ float As[16][128];
    __shared__ float Bs[16][128];

    const int tid = threadIdx.x;
    const int tx = tid & 15, ty = tid >> 4;
    const int bm = blockIdx.y * 128, bn = blockIdx.x * 128;

    float acc[8][8];
#pragma unroll
    for (int i = 0; i < 8; i++)
#pragma unroll
        for (int j = 0; j < 8; j++) acc[i][j] = 0.f;

    for (int k0 = 0; k0 < K; k0 += 16) {
#pragma unroll
        for (int it = 0; it < 2; it++) {
            int qidx = tid + it * 256;          // 0..511
            int row = qidx >> 2;                // 0..127
            int q   = qidx & 3;                 // 0..3
            float4 a = *(const float4*)&A[(size_t)(bm + row) * K + k0 + 4 * q];
            As[4*q+0][row] = a.x; As[4*q+1][row] = a.y;
            As[4*q+2][row] = a.z; As[4*q+3][row] = a.w;
            float4 w = *(const float4*)&W[(size_t)(bn + row) * K + k0 + 4 * q];
            Bs[4*q+0][row] = w.x; Bs[4*q+1][row] = w.y;
            Bs[4*q+2][row] = w.z; Bs[4*q+3][row] = w.w;
        }
        __syncthreads();

#pragma unroll
        for (int kk = 0; kk < 16; kk++) {
            float4 a0 = *(const float4*)&As[kk][8 * ty];
            float4 a1 = *(const float4*)&As[kk][8 * ty + 4];
            float4 b0 = *(const float4*)&Bs[kk][8 * tx];
            float4 b1 = *(const float4*)&Bs[kk][8 * tx + 4];
            float av[8] = {a0.x, a0.y, a0.z, a0.w, a1.x, a1.y, a1.z, a1.w};
            float bv[8] = {b0.x, b0.y, b0.z, b0.w, b1.x, b1.y, b1.z, b1.w};
#pragma unroll
            for (int i = 0; i < 8; i++)
#pragma unroll
                for (int j = 0; j < 8; j++)
                    acc[i][j] += av[i] * bv[j];
        }
        __syncthreads();
    }

#pragma unroll
    for (int i = 0; i < 8; i++) {
        int row = bm + 8 * ty + i;
#pragma unroll
        for (int j = 0; j < 8; j += 4) {
            int col = bn + 8 * tx + j;
            float4 r;
            r.x = acc[i][j+0] + bias[col+0];
            r.y = acc[i][j+1] + bias[col+1];
            r.z = acc[i][j+2] + bias[col+2];
            r.w = acc[i][j+3] + bias[col+3];
            *(float4*)&C[(size_t)row * N + col] = r;
        }
    }
}

// ---------------------------------------------------------------------------
// Flash attention: one block per (kv head-batch, 64-row query tile).
// 64x64 score tiles, online softmax, fp32.
// smem: Qs[64][68], Kts[64][68] (d-major), Ps[64][68], Vs[64][68] = 69632 B
// ---------------------------------------------------------------------------
#define FPAD 68
#define FSMEM_FLOATS (4 * 64 * FPAD)

__global__ __launch_bounds__(256) void flash_k(const unsigned char* __restrict__ mask)
{
    extern __shared__ float sm[];
    float* Qs  = sm;
    float* Kts = sm + 64 * FPAD;       // Kts[d][n]
    float* Ps  = sm + 2 * 64 * FPAD;   // Ps[r][n]
    float* Vs  = sm + 3 * 64 * FPAD;   // Vs[n][c]

    const int tid = threadIdx.x;
    const int tx = tid & 15, ty = tid >> 4;
    const int head = blockIdx.y;           // 0..31 = b*H+h
    const int b = head >> 4, h = head & 15;
    const int q0 = blockIdx.x * 64;

    // --- load Q tile: Qs[r][d] ---
    {
        int r = tid >> 2, q = tid & 3;
        const float* qp = g_qkv + ((size_t)(q0 + r) * BATCH + b) * QKVN + h * HDIM;
#pragma unroll
        for (int it = 0; it < 4; it++) {
            int qq = q + it * 4;
            float4 v = *(const float4*)(qp + 4 * qq);
            *(float4*)&Qs[r * FPAD + 4 * qq] = v;
        }
    }

    float m_i[4], l_i[4], o[4][4];
#pragma unroll
    for (int i = 0; i < 4; i++) {
        m_i[i] = -1e30f; l_i[i] = 0.f;
#pragma unroll
        for (int j = 0; j < 4; j++) o[i][j] = 0.f;
    }

    for (int j0 = 0; j0 < SEQ; j0 += 64) {
        // --- load K (transposed) and V tiles ---
        {
            int r = tid >> 2, q = tid & 3;
            const float* kp = g_qkv + ((size_t)(j0 + r) * BATCH + b) * QKVN + EMB + h * HDIM;
            const float* vp = kp + EMB;
#pragma unroll
            for (int it = 0; it < 4; it++) {
                int qq = q + it * 4;
                float4 kv = *(const float4*)(kp + 4 * qq);
                Kts[(4*qq+0) * FPAD + r] = kv.x;
                Kts[(4*qq+1) * FPAD + r] = kv.y;
                Kts[(4*qq+2) * FPAD + r] = kv.z;
                Kts[(4*qq+3) * FPAD + r] = kv.w;
                float4 vv = *(const float4*)(vp + 4 * qq);
                *(float4*)&Vs[r * FPAD + 4 * qq] = vv;
            }
        }
        __syncthreads();

        // --- S = Q @ K^T for this 64x64 tile, 4x4 per thread ---
        float s[4][4];
#pragma unroll
        for (int i = 0; i < 4; i++)
#pragma unroll
            for (int j = 0; j < 4; j++) s[i][j] = 0.f;

#pragma unroll 8
        for (int d = 0; d < 64; d++) {
            float4 kv = *(const float4*)&Kts[d * FPAD + 4 * tx];
            float qv[4];
#pragma unroll
            for (int i = 0; i < 4; i++) qv[i] = Qs[(4 * ty + i) * FPAD + d];
#pragma unroll
            for (int i = 0; i < 4; i++) {
                s[i][0] += qv[i] * kv.x;
                s[i][1] += qv[i] * kv.y;
                s[i][2] += qv[i] * kv.z;
                s[i][3] += qv[i] * kv.w;
            }
        }

        // --- scale + padding mask ---
        bool mk[4];
#pragma unroll
        for (int j = 0; j < 4; j++)
            mk[j] = mask[b * SEQ + j0 + 4 * tx + j] != 0;
#pragma unroll
        for (int i = 0; i < 4; i++)
#pragma unroll
            for (int j = 0; j < 4; j++)
                s[i][j] = mk[j] ? -1e30f : s[i][j] * 0.125f;

        // --- online softmax (row reductions across 16 tx lanes) ---
#pragma unroll
        for (int i = 0; i < 4; i++) {
            float rm = fmaxf(fmaxf(s[i][0], s[i][1]), fmaxf(s[i][2], s[i][3]));
#pragma unroll
            for (int off = 8; off >= 1; off >>= 1)
                rm = fmaxf(rm, __shfl_xor_sync(0xffffffffu, rm, off));
            float mnew = fmaxf(m_i[i], rm);
            float corr = __expf(m_i[i] - mnew);
            float rs = 0.f;
#pragma unroll
            for (int j = 0; j < 4; j++) {
                s[i][j] = __expf(s[i][j] - mnew);
                rs += s[i][j];
            }
#pragma unroll
            for (int off = 8; off >= 1; off >>= 1)
                rs += __shfl_xor_sync(0xffffffffu, rs, off);
            l_i[i] = l_i[i] * corr + rs;
            m_i[i] = mnew;
#pragma unroll
            for (int j = 0; j < 4; j++) {
                o[i][j] *= corr;
                Ps[(4 * ty + i) * FPAD + 4 * tx + j] = s[i][j];
            }
        }
        __syncthreads();

        // --- O += P @ V ---
#pragma unroll 4
        for (int n = 0; n < 64; n++) {
            float4 vv = *(const float4*)&Vs[n * FPAD + 4 * tx];
#pragma unroll
            for (int i = 0; i < 4; i++) {
                float p = Ps[(4 * ty + i) * FPAD + n];
                o[i][0] += p * vv.x;
                o[i][1] += p * vv.y;
                o[i][2] += p * vv.z;
                o[i][3] += p * vv.w;
            }
        }
        __syncthreads();
    }

    // --- normalize and write to g_attn[(s*B+b)*E + h*64 + c] ---
#pragma unroll
    for (int i = 0; i < 4; i++) {
        float inv = 1.f / l_i[i];
        float4 r;
        r.x = o[i][0] * inv; r.y = o[i][1] * inv;
        r.z = o[i][2] * inv; r.w = o[i][3] * inv;
        *(float4*)&g_attn[((size_t)(q0 + 4 * ty + i) * BATCH + b) * EMB + h * HDIM + 4 * tx] = r;
    }
}

// ---------------------------------------------------------------------------
// Launch
// ---------------------------------------------------------------------------
extern "C" void kernel_launch(void* const* d_in, const int* in_sizes, int n_in,
                              void* d_out, int out_size)
{
    const float*         x    = (const float*)d_in[0];
    const unsigned char* mask = (const unsigned char*)d_in[1];
    const float*         Win  = (const float*)d_in[2];
    const float*         bin  = (const float*)d_in[3];
    const float*         Wout = (const float*)d_in[4];
    const float*         bout = (const float*)d_in[5];
    float*               out  = (float*)d_out;

    float *qkv_ptr = nullptr, *attn_ptr = nullptr;
    cudaGetSymbolAddress((void**)&qkv_ptr, g_qkv);
    cudaGetSymbolAddress((void**)&attn_ptr, g_attn);

    cudaFuncSetAttribute(flash_k, cudaFuncAttributeMaxDynamicSharedMemorySize,
                         FSMEM_FLOATS * (int)sizeof(float));

    // 1) QKV in-projection: [4096,3072] = x[4096,1024] @ Win^T + bin
    dim3 g1(QKVN / 128, MROWS / 128);
    gemm_bias_k<<<g1, 256>>>(x, Win, bin, qkv_ptr, MROWS, QKVN, EMB);

    // 2) attention per (b,h), 64-row query tiles
    dim3 g2(SEQ / 64, BATCH * NHEAD);
    flash_k<<<g2, 256, FSMEM_FLOATS * (int)sizeof(float)>>>(mask);

    // 3) out-projection: out[4096,1024] = g_attn @ Wout^T + bout
    dim3 g3(EMB / 128, MROWS / 128);
    gemm_bias_k<<<g3, 256>>>(attn_ptr, Wout, bout, out, MROWS, EMB, EMB);
}

// round 3
// speedup vs baseline: 1.5763x; 1.5763x over previous
#include <cuda_runtime.h>
#include <cstdint>

// Problem constants: S=2048, B=2, E=1024, H=16, HD=64
#define SEQ   2048
#define BATCH 2
#define EMB   1024
#define NHEAD 16
#define HDIM  64
#define MROWS (SEQ*BATCH)     // 4096
#define QKVN  (3*EMB)         // 3072

// Scratch (allocation-free rule: __device__ globals)
__device__ float g_qkv[(size_t)MROWS * QKVN];    // 48 MB: [m][3E]
__device__ float g_attn[(size_t)MROWS * EMB];    // 16 MB: [m][E]

// ===========================================================================
// helpers
// ===========================================================================
__device__ __forceinline__ uint32_t smem_u32(const void* p) {
    uint32_t a;
    asm("{ .reg .u64 t; cvta.to.shared.u64 t, %1; cvt.u32.u64 %0, t; }" : "=r"(a) : "l"(p));
    return a;
}
__device__ __forceinline__ uint32_t f2tf32(float f) {
    uint32_t u;
    asm("cvt.rn.tf32.f32 %0, %1;" : "=r"(u) : "f"(f));
    return u;
}
__device__ __forceinline__ void ldsm_x4(uint32_t& r0, uint32_t& r1, uint32_t& r2, uint32_t& r3, uint32_t addr) {
    asm volatile("ldmatrix.sync.aligned.m8n8.x4.shared.b16 {%0,%1,%2,%3}, [%4];"
        : "=r"(r0), "=r"(r1), "=r"(r2), "=r"(r3) : "r"(addr));
}
__device__ __forceinline__ void mma_tf32(float* c, const uint32_t* a, uint32_t b0, uint32_t b1) {
    asm volatile(
        "mma.sync.aligned.m16n8k8.row.col.f32.tf32.tf32.f32 "
        "{%0,%1,%2,%3}, {%4,%5,%6,%7}, {%8,%9}, {%0,%1,%2,%3};"
        : "+f"(c[0]), "+f"(c[1]), "+f"(c[2]), "+f"(c[3])
        : "r"(a[0]), "r"(a[1]), "r"(a[2]), "r"(a[3]), "r"(b0), "r"(b1));
}
#define SWZ128(b) ((b) ^ (((b) >> 3) & 0x70))

// ===========================================================================
// TF32 tensor-core GEMM via mma.sync: C[M,N] = A[M,K] @ W[N,K]^T + bias[N]
// 128x128x32 CTA tile, 256 threads (8 warps, 2Mx4N), warp tile 64x32.
// smem tiles SW128-swizzled (row = 128B), double buffered = 64KB dynamic.
// ===========================================================================
#define BK 32
#define TILEB (128 * 128)   // 16KB per tile (128 rows x 32 floats)

__global__ __launch_bounds__(256)
void gemm_tc(const float* __restrict__ A, const float* __restrict__ W,
             const float* __restrict__ bias, float* __restrict__ C,
             int M, int N, int K)
{
    extern __shared__ char sm[];
    const uint32_t sb = smem_u32(sm);
    // buffers: A0 @0, B0 @16K, A1 @32K, B1 @48K
    const int tid  = threadIdx.x;
    const int warp = tid >> 5;
    const int lane = tid & 31;
    const int wm = warp >> 2;          // 0..1
    const int wn = warp & 3;           // 0..3
    const int bm = blockIdx.y * 128, bn = blockIdx.x * 128;
    const int NK = K / BK;

    const int lrow = tid >> 3;         // base row for gmem loads (with +32*it)
    const int lc4  = tid & 7;          // float4 index within 32-float row

    float c[4][4][4];
#pragma unroll
    for (int mi = 0; mi < 4; mi++)
#pragma unroll
        for (int ni = 0; ni < 4; ni++)
#pragma unroll
            for (int q = 0; q < 4; q++) c[mi][ni][q] = 0.f;

    float4 pa[4], pw[4];

    auto fetch = [&](int chunk) {
        const int k0 = chunk * BK + lc4 * 4;
#pragma unroll
        for (int it = 0; it < 4; it++) {
            int row = it * 32 + lrow;
            pa[it] = *(const float4*)&A[(size_t)(bm + row) * K + k0];
            pw[it] = *(const float4*)&W[(size_t)(bn + row) * K + k0];
        }
    };
    auto stash = [&](int buf) {
        const uint32_t ab = sb + buf * 2 * TILEB;
        const uint32_t wb = ab + TILEB;
#pragma unroll
        for (int it = 0; it < 4; it++) {
            int row = it * 32 + lrow;
            uint32_t bo = SWZ128((uint32_t)(row * 128 + lc4 * 16));
            uint4 ua = {f2tf32(pa[it].x), f2tf32(pa[it].y), f2tf32(pa[it].z), f2tf32(pa[it].w)};
            asm volatile("st.shared.v4.b32 [%0], {%1,%2,%3,%4};"
                :: "r"(ab + bo), "r"(ua.x), "r"(ua.y), "r"(ua.z), "r"(ua.w) : "memory");
            uint4 uw = {f2tf32(pw[it].x), f2tf32(pw[it].y), f2tf32(pw[it].z), f2tf32(pw[it].w)};
            asm volatile("st.shared.v4.b32 [%0], {%1,%2,%3,%4};"
                :: "r"(wb + bo), "r"(uw.x), "r"(uw.y), "r"(uw.z), "r"(uw.w) : "memory");
        }
    };

    // ldmatrix lane addressing: row = frag_row0 + (lane&15), kbyte += (lane>>4)*16
    const int lrow16 = lane & 15;
    const int lkhalf = (lane >> 4) * 16;

    auto compute = [&](int buf) {
        const uint32_t ab = sb + buf * 2 * TILEB;
        const uint32_t wb = ab + TILEB;
#pragma unroll
        for (int ks = 0; ks < 4; ks++) {
            const uint32_t kb = ks * 32 + lkhalf;
            uint32_t a[4][4];
#pragma unroll
            for (int mi = 0; mi < 4; mi++) {
                int row = wm * 64 + mi * 16 + lrow16;
                uint32_t addr = ab + SWZ128((uint32_t)(row * 128) + kb);
                ldsm_x4(a[mi][0], a[mi][1], a[mi][2], a[mi][3], addr);
            }
            uint32_t b0[4], b1[4];
#pragma unroll
            for (int p = 0; p < 2; p++) {
                int row = wn * 32 + p * 16 + lrow16;
                uint32_t addr = wb + SWZ128((uint32_t)(row * 128) + kb);
                ldsm_x4(b0[2*p], b0[2*p+1], b1[2*p], b1[2*p+1], addr);
            }
#pragma unroll
            for (int mi = 0; mi < 4; mi++)
#pragma unroll
                for (int ni = 0; ni < 4; ni++)
                    mma_tf32(c[mi][ni], a[mi], b0[ni], b1[ni]);
        }
    };

    // software pipeline
    fetch(0);
    stash(0);
    __syncthreads();
    for (int k = 0; k < NK; k++) {
        if (k + 1 < NK) fetch(k + 1);
        compute(k & 1);
        if (k + 1 < NK) {
            stash((k + 1) & 1);
            __syncthreads();
        }
    }

    // epilogue: fragment layout c0=C[g][q*2], c1=+1, c2=C[g+8][q*2], c3=+1
    const int g = lane >> 2, qd = lane & 3;
#pragma unroll
    for (int ni = 0; ni < 4; ni++) {
        int col = bn + wn * 32 + ni * 8 + qd * 2;
        float bz0 = bias[col], bz1 = bias[col + 1];
#pragma unroll
        for (int mi = 0; mi < 4; mi++) {
            int row = bm + wm * 64 + mi * 16 + g;
            float2 v0 = {c[mi][ni][0] + bz0, c[mi][ni][1] + bz1};
            *(float2*)&C[(size_t)row * N + col] = v0;
            float2 v1 = {c[mi][ni][2] + bz0, c[mi][ni][3] + bz1};
            *(float2*)&C[(size_t)(row + 8) * N + col] = v1;
        }
    }
}
#define GSMEM_TOTAL (4 * TILEB)

// ---------------------------------------------------------------------------
// Flash attention (unchanged): one block per (head-batch, 64-row query tile)
// ---------------------------------------------------------------------------
#define FPAD 68
#define FSMEM_FLOATS (4 * 64 * FPAD)

__global__ __launch_bounds__(256) void flash_k(const unsigned char* __restrict__ mask)
{
    extern __shared__ float smf[];
    float* Qs  = smf;
    float* Kts = smf + 64 * FPAD;
    float* Ps  = smf + 2 * 64 * FPAD;
    float* Vs  = smf + 3 * 64 * FPAD;

    const int tid = threadIdx.x;
    const int tx = tid & 15, ty = tid >> 4;
    const int head = blockIdx.y;
    const int b = head >> 4, h = head & 15;
    const int q0 = blockIdx.x * 64;

    {
        int r = tid >> 2, q = tid & 3;
        const float* qp = g_qkv + ((size_t)(q0 + r) * BATCH + b) * QKVN + h * HDIM;
#pragma unroll
        for (int it = 0; it < 4; it++) {
            int qq = q + it * 4;
            float4 v = *(const float4*)(qp + 4 * qq);
            *(float4*)&Qs[r * FPAD + 4 * qq] = v;
        }
    }

    float m_i[4], l_i[4], o[4][4];
#pragma unroll
    for (int i = 0; i < 4; i++) {
        m_i[i] = -1e30f; l_i[i] = 0.f;
#pragma unroll
        for (int j = 0; j < 4; j++) o[i][j] = 0.f;
    }

    for (int j0 = 0; j0 < SEQ; j0 += 64) {
        {
            int r = tid >> 2, q = tid & 3;
            const float* kp = g_qkv + ((size_t)(j0 + r) * BATCH + b) * QKVN + EMB + h * HDIM;
            const float* vp = kp + EMB;
#pragma unroll
            for (int it = 0; it < 4; it++) {
                int qq = q + it * 4;
                float4 kv = *(const float4*)(kp + 4 * qq);
                Kts[(4*qq+0) * FPAD + r] = kv.x;
                Kts[(4*qq+1) * FPAD + r] = kv.y;
                Kts[(4*qq+2) * FPAD + r] = kv.z;
                Kts[(4*qq+3) * FPAD + r] = kv.w;
                float4 vv = *(const float4*)(vp + 4 * qq);
                *(float4*)&Vs[r * FPAD + 4 * qq] = vv;
            }
        }
        __syncthreads();

        float s[4][4];
#pragma unroll
        for (int i = 0; i < 4; i++)
#pragma unroll
            for (int j = 0; j < 4; j++) s[i][j] = 0.f;

#pragma unroll 8
        for (int d = 0; d < 64; d++) {
            float4 kv = *(const float4*)&Kts[d * FPAD + 4 * tx];
            float qv[4];
#pragma unroll
            for (int i = 0; i < 4; i++) qv[i] = Qs[(4 * ty + i) * FPAD + d];
#pragma unroll
            for (int i = 0; i < 4; i++) {
                s[i][0] += qv[i] * kv.x;
                s[i][1] += qv[i] * kv.y;
                s[i][2] += qv[i] * kv.z;
                s[i][3] += qv[i] * kv.w;
            }
        }

        bool mk[4];
#pragma unroll
        for (int j = 0; j < 4; j++)
            mk[j] = mask[b * SEQ + j0 + 4 * tx + j] != 0;
#pragma unroll
        for (int i = 0; i < 4; i++)
#pragma unroll
            for (int j = 0; j < 4; j++)
                s[i][j] = mk[j] ? -1e30f : s[i][j] * 0.125f;

#pragma unroll
        for (int i = 0; i < 4; i++) {
            float rm = fmaxf(fmaxf(s[i][0], s[i][1]), fmaxf(s[i][2], s[i][3]));
#pragma unroll
            for (int off = 8; off >= 1; off >>= 1)
                rm = fmaxf(rm, __shfl_xor_sync(0xffffffffu, rm, off));
            float mnew = fmaxf(m_i[i], rm);
            float corr = __expf(m_i[i] - mnew);
            float rs = 0.f;
#pragma unroll
            for (int j = 0; j < 4; j++) {
                s[i][j] = __expf(s[i][j] - mnew);
                rs += s[i][j];
            }
#pragma unroll
            for (int off = 8; off >= 1; off >>= 1)
                rs += __shfl_xor_sync(0xffffffffu, rs, off);
            l_i[i] = l_i[i] * corr + rs;
            m_i[i] = mnew;
#pragma unroll
            for (int j = 0; j < 4; j++) {
                o[i][j] *= corr;
                Ps[(4 * ty + i) * FPAD + 4 * tx + j] = s[i][j];
            }
        }
        __syncthreads();

#pragma unroll 4
        for (int n = 0; n < 64; n++) {
            float4 vv = *(const float4*)&Vs[n * FPAD + 4 * tx];
#pragma unroll
            for (int i = 0; i < 4; i++) {
                float p = Ps[(4 * ty + i) * FPAD + n];
                o[i][0] += p * vv.x;
                o[i][1] += p * vv.y;
                o[i][2] += p * vv.z;
                o[i][3] += p * vv.w;
            }
        }
        __syncthreads();
    }

#pragma unroll
    for (int i = 0; i < 4; i++) {
        float inv = 1.f / l_i[i];
        float4 r;
        r.x = o[i][0] * inv; r.y = o[i][1] * inv;
        r.z = o[i][2] * inv; r.w = o[i][3] * inv;
        *(float4*)&g_attn[((size_t)(q0 + 4 * ty + i) * BATCH + b) * EMB + h * HDIM + 4 * tx] = r;
    }
}

// ---------------------------------------------------------------------------
// Launch
// ---------------------------------------------------------------------------
extern "C" void kernel_launch(void* const* d_in, const int* in_sizes, int n_in,
                              void* d_out, int out_size)
{
    const float*         x    = (const float*)d_in[0];
    const unsigned char* mask = (const unsigned char*)d_in[1];
    const float*         Win  = (const float*)d_in[2];
    const float*         bin  = (const float*)d_in[3];
    const float*         Wout = (const float*)d_in[4];
    const float*         bout = (const float*)d_in[5];
    float*               out  = (float*)d_out;

    float *qkv_ptr = nullptr, *attn_ptr = nullptr;
    cudaGetSymbolAddress((void**)&qkv_ptr, g_qkv);
    cudaGetSymbolAddress((void**)&attn_ptr, g_attn);

    cudaFuncSetAttribute(gemm_tc, cudaFuncAttributeMaxDynamicSharedMemorySize, GSMEM_TOTAL);
    cudaFuncSetAttribute(flash_k, cudaFuncAttributeMaxDynamicSharedMemorySize,
                         FSMEM_FLOATS * (int)sizeof(float));

    // 1) QKV in-projection: [4096,3072] = x @ Win^T + bin   (mma.sync tf32)
    dim3 g1(QKVN / 128, MROWS / 128);
    gemm_tc<<<g1, 256, GSMEM_TOTAL>>>(x, Win, bin, qkv_ptr, MROWS, QKVN, EMB);

    // 2) attention per (b,h), 64-row query tiles (SIMT fp32)
    dim3 g2(SEQ / 64, BATCH * NHEAD);
    flash_k<<<g2, 256, FSMEM_FLOATS * (int)sizeof(float)>>>(mask);

    // 3) out-projection: out = g_attn @ Wout^T + bout       (mma.sync tf32)
    dim3 g3(EMB / 128, MROWS / 128);
    gemm_tc<<<g3, 256, GSMEM_TOTAL>>>(attn_ptr, Wout, bout, out, MROWS, EMB, EMB);
}

// round 4
// speedup vs baseline: 1.5795x; 1.0021x over previous
#include <cuda_runtime.h>
#include <cstdint>

// Problem constants: S=2048, B=2, E=1024, H=16, HD=64
#define SEQ   2048
#define BATCH 2
#define EMB   1024
#define NHEAD 16
#define HDIM  64
#define MROWS (SEQ*BATCH)     // 4096
#define QKVN  (3*EMB)         // 3072

// Scratch (allocation-free rule: __device__ globals)
__device__ float g_qkv[(size_t)MROWS * QKVN];    // 48 MB: [m][3E]
__device__ float g_attn[(size_t)MROWS * EMB];    // 16 MB: [m][E]

// ===========================================================================
// helpers
// ===========================================================================
__device__ __forceinline__ uint32_t smem_u32(const void* p) {
    uint32_t a;
    asm("{ .reg .u64 t; cvta.to.shared.u64 t, %1; cvt.u32.u64 %0, t; }" : "=r"(a) : "l"(p));
    return a;
}
__device__ __forceinline__ uint32_t f2tf32(float f) {
    uint32_t u;
    asm("cvt.rn.tf32.f32 %0, %1;" : "=r"(u) : "f"(f));
    return u;
}
__device__ __forceinline__ void ldsm_x4(uint32_t& r0, uint32_t& r1, uint32_t& r2, uint32_t& r3, uint32_t addr) {
    asm volatile("ldmatrix.sync.aligned.m8n8.x4.shared.b16 {%0,%1,%2,%3}, [%4];"
        : "=r"(r0), "=r"(r1), "=r"(r2), "=r"(r3) : "r"(addr));
}
__device__ __forceinline__ void mma_tf32(float* c, const uint32_t* a, uint32_t b0, uint32_t b1) {
    asm volatile(
        "mma.sync.aligned.m16n8k8.row.col.f32.tf32.tf32.f32 "
        "{%0,%1,%2,%3}, {%4,%5,%6,%7}, {%8,%9}, {%0,%1,%2,%3};"
        : "+f"(c[0]), "+f"(c[1]), "+f"(c[2]), "+f"(c[3])
        : "r"(a[0]), "r"(a[1]), "r"(a[2]), "r"(a[3]), "r"(b0), "r"(b1));
}
#define SWZ128(b) ((b) ^ (((b) >> 3) & 0x70))

// ===========================================================================
// TF32 tensor-core GEMM via mma.sync: C[M,N] = A[M,K] @ W[N,K]^T + bias[N]
// 128x128x32 CTA tile, 256 threads (8 warps, 2Mx4N), warp tile 64x32.
// smem tiles SW128-swizzled (row = 128B), double buffered = 64KB dynamic.
// ===========================================================================
#define BK 32
#define TILEB (128 * 128)   // 16KB per tile (128 rows x 32 floats)

__global__ __launch_bounds__(256)
void gemm_tc(const float* __restrict__ A, const float* __restrict__ W,
             const float* __restrict__ bias, float* __restrict__ C,
             int M, int N, int K)
{
    extern __shared__ char sm[];
    const uint32_t sb = smem_u32(sm);
    // buffers: A0 @0, B0 @16K, A1 @32K, B1 @48K
    const int tid  = threadIdx.x;
    const int warp = tid >> 5;
    const int lane = tid & 31;
    const int wm = warp >> 2;          // 0..1
    const int wn = warp & 3;           // 0..3
    const int bm = blockIdx.y * 128, bn = blockIdx.x * 128;
    const int NK = K / BK;

    const int lrow = tid >> 3;         // base row for gmem loads (with +32*it)
    const int lc4  = tid & 7;          // float4 index within 32-float row

    float c[4][4][4];
#pragma unroll
    for (int mi = 0; mi < 4; mi++)
#pragma unroll
        for (int ni = 0; ni < 4; ni++)
#pragma unroll
            for (int q = 0; q < 4; q++) c[mi][ni][q] = 0.f;

    float4 pa[4], pw[4];

    auto fetch = [&](int chunk) {
        const int k0 = chunk * BK + lc4 * 4;
#pragma unroll
        for (int it = 0; it < 4; it++) {
            int row = it * 32 + lrow;
            pa[it] = *(const float4*)&A[(size_t)(bm + row) * K + k0];
            pw[it] = *(const float4*)&W[(size_t)(bn + row) * K + k0];
        }
    };
    auto stash = [&](int buf) {
        const uint32_t ab = sb + buf * 2 * TILEB;
        const uint32_t wb = ab + TILEB;
#pragma unroll
        for (int it = 0; it < 4; it++) {
            int row = it * 32 + lrow;
            uint32_t bo = SWZ128((uint32_t)(row * 128 + lc4 * 16));
            uint4 ua = {f2tf32(pa[it].x), f2tf32(pa[it].y), f2tf32(pa[it].z), f2tf32(pa[it].w)};
            asm volatile("st.shared.v4.b32 [%0], {%1,%2,%3,%4};"
                :: "r"(ab + bo), "r"(ua.x), "r"(ua.y), "r"(ua.z), "r"(ua.w) : "memory");
            uint4 uw = {f2tf32(pw[it].x), f2tf32(pw[it].y), f2tf32(pw[it].z), f2tf32(pw[it].w)};
            asm volatile("st.shared.v4.b32 [%0], {%1,%2,%3,%4};"
                :: "r"(wb + bo), "r"(uw.x), "r"(uw.y), "r"(uw.z), "r"(uw.w) : "memory");
        }
    };

    // ldmatrix lane addressing: row = frag_row0 + (lane&15), kbyte += (lane>>4)*16
    const int lrow16 = lane & 15;
    const int lkhalf = (lane >> 4) * 16;

    auto compute = [&](int buf) {
        const uint32_t ab = sb + buf * 2 * TILEB;
        const uint32_t wb = ab + TILEB;
#pragma unroll
        for (int ks = 0; ks < 4; ks++) {
            const uint32_t kb = ks * 32 + lkhalf;
            uint32_t a[4][4];
#pragma unroll
            for (int mi = 0; mi < 4; mi++) {
                int row = wm * 64 + mi * 16 + lrow16;
                uint32_t addr = ab + SWZ128((uint32_t)(row * 128) + kb);
                ldsm_x4(a[mi][0], a[mi][1], a[mi][2], a[mi][3], addr);
            }
            uint32_t b0[4], b1[4];
#pragma unroll
            for (int p = 0; p < 2; p++) {
                int row = wn * 32 + p * 16 + lrow16;
                uint32_t addr = wb + SWZ128((uint32_t)(row * 128) + kb);
                ldsm_x4(b0[2*p], b0[2*p+1], b1[2*p], b1[2*p+1], addr);
            }
#pragma unroll
            for (int mi = 0; mi < 4; mi++)
#pragma unroll
                for (int ni = 0; ni < 4; ni++)
                    mma_tf32(c[mi][ni], a[mi], b0[ni], b1[ni]);
        }
    };

    // software pipeline
    fetch(0);
    stash(0);
    __syncthreads();
    for (int k = 0; k < NK; k++) {
        if (k + 1 < NK) fetch(k + 1);
        compute(k & 1);
        if (k + 1 < NK) {
            stash((k + 1) & 1);
            __syncthreads();
        }
    }

    // epilogue: fragment layout c0=C[g][q*2], c1=+1, c2=C[g+8][q*2], c3=+1
    const int g = lane >> 2, qd = lane & 3;
#pragma unroll
    for (int ni = 0; ni < 4; ni++) {
        int col = bn + wn * 32 + ni * 8 + qd * 2;
        float bz0 = bias[col], bz1 = bias[col + 1];
#pragma unroll
        for (int mi = 0; mi < 4; mi++) {
            int row = bm + wm * 64 + mi * 16 + g;
            float2 v0 = {c[mi][ni][0] + bz0, c[mi][ni][1] + bz1};
            *(float2*)&C[(size_t)row * N + col] = v0;
            float2 v1 = {c[mi][ni][2] + bz0, c[mi][ni][3] + bz1};
            *(float2*)&C[(size_t)(row + 8) * N + col] = v1;
        }
    }
}
#define GSMEM_TOTAL (4 * TILEB)

// ---------------------------------------------------------------------------
// Flash attention (unchanged): one block per (head-batch, 64-row query tile)
// ---------------------------------------------------------------------------
#define FPAD 68
#define FSMEM_FLOATS (4 * 64 * FPAD)

__global__ __launch_bounds__(256) void flash_k(const unsigned char* __restrict__ mask)
{
    extern __shared__ float smf[];
    float* Qs  = smf;
    float* Kts = smf + 64 * FPAD;
    float* Ps  = smf + 2 * 64 * FPAD;
    float* Vs  = smf + 3 * 64 * FPAD;

    const int tid = threadIdx.x;
    const int tx = tid & 15, ty = tid >> 4;
    const int head = blockIdx.y;
    const int b = head >> 4, h = head & 15;
    const int q0 = blockIdx.x * 64;

    {
        int r = tid >> 2, q = tid & 3;
        const float* qp = g_qkv + ((size_t)(q0 + r) * BATCH + b) * QKVN + h * HDIM;
#pragma unroll
        for (int it = 0; it < 4; it++) {
            int qq = q + it * 4;
            float4 v = *(const float4*)(qp + 4 * qq);
            *(float4*)&Qs[r * FPAD + 4 * qq] = v;
        }
    }

    float m_i[4], l_i[4], o[4][4];
#pragma unroll
    for (int i = 0; i < 4; i++) {
        m_i[i] = -1e30f; l_i[i] = 0.f;
#pragma unroll
        for (int j = 0; j < 4; j++) o[i][j] = 0.f;
    }

    for (int j0 = 0; j0 < SEQ; j0 += 64) {
        {
            int r = tid >> 2, q = tid & 3;
            const float* kp = g_qkv + ((size_t)(j0 + r) * BATCH + b) * QKVN + EMB + h * HDIM;
            const float* vp = kp + EMB;
#pragma unroll
            for (int it = 0; it < 4; it++) {
                int qq = q + it * 4;
                float4 kv = *(const float4*)(kp + 4 * qq);
                Kts[(4*qq+0) * FPAD + r] = kv.x;
                Kts[(4*qq+1) * FPAD + r] = kv.y;
                Kts[(4*qq+2) * FPAD + r] = kv.z;
                Kts[(4*qq+3) * FPAD + r] = kv.w;
                float4 vv = *(const float4*)(vp + 4 * qq);
                *(float4*)&Vs[r * FPAD + 4 * qq] = vv;
            }
        }
        __syncthreads();

        float s[4][4];
#pragma unroll
        for (int i = 0; i < 4; i++)
#pragma unroll
            for (int j = 0; j < 4; j++) s[i][j] = 0.f;

#pragma unroll 8
        for (int d = 0; d < 64; d++) {
            float4 kv = *(const float4*)&Kts[d * FPAD + 4 * tx];
            float qv[4];
#pragma unroll
            for (int i = 0; i < 4; i++) qv[i] = Qs[(4 * ty + i) * FPAD + d];
#pragma unroll
            for (int i = 0; i < 4; i++) {
                s[i][0] += qv[i] * kv.x;
                s[i][1] += qv[i] * kv.y;
                s[i][2] += qv[i] * kv.z;
                s[i][3] += qv[i] * kv.w;
            }
        }

        bool mk[4];
#pragma unroll
        for (int j = 0; j < 4; j++)
            mk[j] = mask[b * SEQ + j0 + 4 * tx + j] != 0;
#pragma unroll
        for (int i = 0; i < 4; i++)
#pragma unroll
            for (int j = 0; j < 4; j++)
                s[i][j] = mk[j] ? -1e30f : s[i][j] * 0.125f;

#pragma unroll
        for (int i = 0; i < 4; i++) {
            float rm = fmaxf(fmaxf(s[i][0], s[i][1]), fmaxf(s[i][2], s[i][3]));
#pragma unroll
            for (int off = 8; off >= 1; off >>= 1)
                rm = fmaxf(rm, __shfl_xor_sync(0xffffffffu, rm, off));
            float mnew = fmaxf(m_i[i], rm);
            float corr = __expf(m_i[i] - mnew);
            float rs = 0.f;
#pragma unroll
            for (int j = 0; j < 4; j++) {
                s[i][j] = __expf(s[i][j] - mnew);
                rs += s[i][j];
            }
#pragma unroll
            for (int off = 8; off >= 1; off >>= 1)
                rs += __shfl_xor_sync(0xffffffffu, rs, off);
            l_i[i] = l_i[i] * corr + rs;
            m_i[i] = mnew;
#pragma unroll
            for (int j = 0; j < 4; j++) {
                o[i][j] *= corr;
                Ps[(4 * ty + i) * FPAD + 4 * tx + j] = s[i][j];
            }
        }
        __syncthreads();

#pragma unroll 4
        for (int n = 0; n < 64; n++) {
            float4 vv = *(const float4*)&Vs[n * FPAD + 4 * tx];
#pragma unroll
            for (int i = 0; i < 4; i++) {
                float p = Ps[(4 * ty + i) * FPAD + n];
                o[i][0] += p * vv.x;
                o[i][1] += p * vv.y;
                o[i][2] += p * vv.z;
                o[i][3] += p * vv.w;
            }
        }
        __syncthreads();
    }

#pragma unroll
    for (int i = 0; i < 4; i++) {
        float inv = 1.f / l_i[i];
        float4 r;
        r.x = o[i][0] * inv; r.y = o[i][1] * inv;
        r.z = o[i][2] * inv; r.w = o[i][3] * inv;
        *(float4*)&g_attn[((size_t)(q0 + 4 * ty + i) * BATCH + b) * EMB + h * HDIM + 4 * tx] = r;
    }
}

// ---------------------------------------------------------------------------
// Launch
// ---------------------------------------------------------------------------
extern "C" void kernel_launch(void* const* d_in, const int* in_sizes, int n_in,
                              void* d_out, int out_size)
{
    const float*         x    = (const float*)d_in[0];
    const unsigned char* mask = (const unsigned char*)d_in[1];
    const float*         Win  = (const float*)d_in[2];
    const float*         bin  = (const float*)d_in[3];
    const float*         Wout = (const float*)d_in[4];
    const float*         bout = (const float*)d_in[5];
    float*               out  = (float*)d_out;

    float *qkv_ptr = nullptr, *attn_ptr = nullptr;
    cudaGetSymbolAddress((void**)&qkv_ptr, g_qkv);
    cudaGetSymbolAddress((void**)&attn_ptr, g_attn);

    cudaFuncSetAttribute(gemm_tc, cudaFuncAttributeMaxDynamicSharedMemorySize, GSMEM_TOTAL);
    cudaFuncSetAttribute(flash_k, cudaFuncAttributeMaxDynamicSharedMemorySize,
                         FSMEM_FLOATS * (int)sizeof(float));

    // 1) QKV in-projection: [4096,3072] = x @ Win^T + bin   (mma.sync tf32)
    dim3 g1(QKVN / 128, MROWS / 128);
    gemm_tc<<<g1, 256, GSMEM_TOTAL>>>(x, Win, bin, qkv_ptr, MROWS, QKVN, EMB);

    // 2) attention per (b,h), 64-row query tiles (SIMT fp32)
    dim3 g2(SEQ / 64, BATCH * NHEAD);
    flash_k<<<g2, 256, FSMEM_FLOATS * (int)sizeof(float)>>>(mask);

    // 3) out-projection: out = g_attn @ Wout^T + bout       (mma.sync tf32)
    dim3 g3(EMB / 128, MROWS / 128);
    gemm_tc<<<g3, 256, GSMEM_TOTAL>>>(attn_ptr, Wout, bout, out, MROWS, EMB, EMB);
}

// round 5
// speedup vs baseline: 2.8041x; 1.7753x over previous
#include <cuda_runtime.h>
#include <cstdint>

// Problem constants: S=2048, B=2, E=1024, H=16, HD=64
#define SEQ   2048
#define BATCH 2
#define EMB   1024
#define NHEAD 16
#define HDIM  64
#define MROWS (SEQ*BATCH)     // 4096
#define QKVN  (3*EMB)         // 3072

__device__ float g_qkv[(size_t)MROWS * QKVN];    // 48 MB: [m][3E]
__device__ float g_attn[(size_t)MROWS * EMB];    // 16 MB: [m][E]

// ===========================================================================
// helpers
// ===========================================================================
__device__ __forceinline__ uint32_t smem_u32(const void* p) {
    uint32_t a;
    asm("{ .reg .u64 t; cvta.to.shared.u64 t, %1; cvt.u32.u64 %0, t; }" : "=r"(a) : "l"(p));
    return a;
}
__device__ __forceinline__ uint32_t f2tf32(float f) {
    uint32_t u;
    asm("cvt.rn.tf32.f32 %0, %1;" : "=r"(u) : "f"(f));
    return u;
}
__device__ __forceinline__ void ldsm_x4(uint32_t& r0, uint32_t& r1, uint32_t& r2, uint32_t& r3, uint32_t addr) {
    asm volatile("ldmatrix.sync.aligned.m8n8.x4.shared.b16 {%0,%1,%2,%3}, [%4];"
        : "=r"(r0), "=r"(r1), "=r"(r2), "=r"(r3) : "r"(addr));
}
__device__ __forceinline__ void mma_tf32(float* c, const uint32_t* a, uint32_t b0, uint32_t b1) {
    asm volatile(
        "mma.sync.aligned.m16n8k8.row.col.f32.tf32.tf32.f32 "
        "{%0,%1,%2,%3}, {%4,%5,%6,%7}, {%8,%9}, {%0,%1,%2,%3};"
        : "+f"(c[0]), "+f"(c[1]), "+f"(c[2]), "+f"(c[3])
        : "r"(a[0]), "r"(a[1]), "r"(a[2]), "r"(a[3]), "r"(b0), "r"(b1));
}
#define SWZ128(b) ((b) ^ (((b) >> 3) & 0x70))

// ===========================================================================
// TF32 GEMM via mma.sync (unchanged from R4): C = A @ W^T + bias
// ===========================================================================
#define BK 32
#define TILEB (128 * 128)

__global__ __launch_bounds__(256)
void gemm_tc(const float* __restrict__ A, const float* __restrict__ W,
             const float* __restrict__ bias, float* __restrict__ C,
             int M, int N, int K)
{
    extern __shared__ char sm[];
    const uint32_t sb = smem_u32(sm);
    const int tid  = threadIdx.x;
    const int warp = tid >> 5;
    const int lane = tid & 31;
    const int wm = warp >> 2;
    const int wn = warp & 3;
    const int bm = blockIdx.y * 128, bn = blockIdx.x * 128;
    const int NK = K / BK;

    const int lrow = tid >> 3;
    const int lc4  = tid & 7;

    float c[4][4][4];
#pragma unroll
    for (int mi = 0; mi < 4; mi++)
#pragma unroll
        for (int ni = 0; ni < 4; ni++)
#pragma unroll
            for (int q = 0; q < 4; q++) c[mi][ni][q] = 0.f;

    float4 pa[4], pw[4];

    auto fetch = [&](int chunk) {
        const int k0 = chunk * BK + lc4 * 4;
#pragma unroll
        for (int it = 0; it < 4; it++) {
            int row = it * 32 + lrow;
            pa[it] = *(const float4*)&A[(size_t)(bm + row) * K + k0];
            pw[it] = *(const float4*)&W[(size_t)(bn + row) * K + k0];
        }
    };
    auto stash = [&](int buf) {
        const uint32_t ab = sb + buf * 2 * TILEB;
        const uint32_t wb = ab + TILEB;
#pragma unroll
        for (int it = 0; it < 4; it++) {
            int row = it * 32 + lrow;
            uint32_t bo = SWZ128((uint32_t)(row * 128 + lc4 * 16));
            uint4 ua = {f2tf32(pa[it].x), f2tf32(pa[it].y), f2tf32(pa[it].z), f2tf32(pa[it].w)};
            asm volatile("st.shared.v4.b32 [%0], {%1,%2,%3,%4};"
                :: "r"(ab + bo), "r"(ua.x), "r"(ua.y), "r"(ua.z), "r"(ua.w) : "memory");
            uint4 uw = {f2tf32(pw[it].x), f2tf32(pw[it].y), f2tf32(pw[it].z), f2tf32(pw[it].w)};
            asm volatile("st.shared.v4.b32 [%0], {%1,%2,%3,%4};"
                :: "r"(wb + bo), "r"(uw.x), "r"(uw.y), "r"(uw.z), "r"(uw.w) : "memory");
        }
    };

    const int lrow16 = lane & 15;
    const int lkhalf = (lane >> 4) * 16;

    auto compute = [&](int buf) {
        const uint32_t ab = sb + buf * 2 * TILEB;
        const uint32_t wb = ab + TILEB;
#pragma unroll
        for (int ks = 0; ks < 4; ks++) {
            const uint32_t kb = ks * 32 + lkhalf;
            uint32_t a[4][4];
#pragma unroll
            for (int mi = 0; mi < 4; mi++) {
                int row = wm * 64 + mi * 16 + lrow16;
                uint32_t addr = ab + SWZ128((uint32_t)(row * 128) + kb);
                ldsm_x4(a[mi][0], a[mi][1], a[mi][2], a[mi][3], addr);
            }
            uint32_t b0[4], b1[4];
#pragma unroll
            for (int p = 0; p < 2; p++) {
                int row = wn * 32 + p * 16 + lrow16;
                uint32_t addr = wb + SWZ128((uint32_t)(row * 128) + kb);
                ldsm_x4(b0[2*p], b0[2*p+1], b1[2*p], b1[2*p+1], addr);
            }
#pragma unroll
            for (int mi = 0; mi < 4; mi++)
#pragma unroll
                for (int ni = 0; ni < 4; ni++)
                    mma_tf32(c[mi][ni], a[mi], b0[ni], b1[ni]);
        }
    };

    fetch(0);
    stash(0);
    __syncthreads();
    for (int k = 0; k < NK; k++) {
        if (k + 1 < NK) fetch(k + 1);
        compute(k & 1);
        if (k + 1 < NK) {
            stash((k + 1) & 1);
            __syncthreads();
        }
    }

    const int g = lane >> 2, qd = lane & 3;
#pragma unroll
    for (int ni = 0; ni < 4; ni++) {
        int col = bn + wn * 32 + ni * 8 + qd * 2;
        float bz0 = bias[col], bz1 = bias[col + 1];
#pragma unroll
        for (int mi = 0; mi < 4; mi++) {
            int row = bm + wm * 64 + mi * 16 + g;
            float2 v0 = {c[mi][ni][0] + bz0, c[mi][ni][1] + bz1};
            *(float2*)&C[(size_t)row * N + col] = v0;
            float2 v1 = {c[mi][ni][2] + bz0, c[mi][ni][3] + bz1};
            *(float2*)&C[(size_t)(row + 8) * N + col] = v1;
        }
    }
}
#define GSMEM_TOTAL (4 * TILEB)

// ===========================================================================
// Tensor-core flash attention (tf32 mma.sync)
// 128 q-rows per CTA, 8 warps x 16-row strips, BKV=64 per iteration.
// smem rows padded to 68 floats (272B): conflict-free ldmatrix.
// ===========================================================================
#define FSTR 272                       // row stride bytes (68 floats)
#define QS_OFF 0
#define KS_OFF (128 * FSTR)            // 34816
#define VT_OFF (KS_OFF + 64 * FSTR)    // 52224
#define PS_OFF (VT_OFF + 64 * FSTR)    // 69632
#define FATT_SMEM (PS_OFF + 128 * FSTR) // 104448

__global__ __launch_bounds__(256, 2)
void flash_tc(const unsigned char* __restrict__ mask)
{
    extern __shared__ char sm[];
    const uint32_t sb = smem_u32(sm);
    const uint32_t qsb = sb + QS_OFF, ksb = sb + KS_OFF, vtb = sb + VT_OFF, psb = sb + PS_OFF;

    const int tid  = threadIdx.x;
    const int warp = tid >> 5;
    const int lane = tid & 31;
    const int g  = lane >> 2;          // 0..7 fragment row
    const int qd = lane & 3;           // 0..3 fragment col group
    const int lrow16 = lane & 15;
    const int lk16   = (lane >> 4) * 16;

    const int head = blockIdx.y;       // b*H + h
    const int b = head >> 4, h = head & 15;
    const int q0 = blockIdx.x * 128;
    const int wr = warp * 16;          // warp's q-row base in tile

    // ---- load Q tile (128 x 64), scale by 1/8, tf32, to Qs ----
    {
        const int r = tid >> 1, half = tid & 1;
        const float* qp = g_qkv + ((size_t)(q0 + r) * BATCH + b) * QKVN + h * HDIM + half * 32;
#pragma unroll
        for (int jj = 0; jj < 8; jj++) {
            float4 v = *(const float4*)(qp + 4 * jj);
            uint4 u = {f2tf32(v.x * 0.125f), f2tf32(v.y * 0.125f),
                       f2tf32(v.z * 0.125f), f2tf32(v.w * 0.125f)};
            asm volatile("st.shared.v4.b32 [%0], {%1,%2,%3,%4};"
                :: "r"(qsb + r * FSTR + (half * 32 + 4 * jj) * 4),
                   "r"(u.x), "r"(u.y), "r"(u.z), "r"(u.w) : "memory");
        }
    }
    __syncthreads();

    // persistent state
    float O[8][4];
#pragma unroll
    for (int nt = 0; nt < 8; nt++)
#pragma unroll
        for (int q = 0; q < 4; q++) O[nt][q] = 0.f;
    float m0 = -1e30f, m1 = -1e30f, l0 = 0.f, l1 = 0.f;

    // ldmatrix base addrs
    const uint32_t a_q = qsb + (wr + lrow16) * FSTR + lk16;
    const uint32_t a_k = ksb + lrow16 * FSTR + lk16;
    const uint32_t a_p = psb + (wr + lrow16) * FSTR + lk16;
    const uint32_t a_v = vtb + lrow16 * FSTR + lk16;

    const int ldr = tid >> 2;          // 0..63 kv row for loads
    const int ldc = tid & 3;           // 0..3

    for (int j0 = 0; j0 < SEQ; j0 += 64) {
        // ---- load K (row-major) and V (transposed) tiles ----
        {
            const float* kp = g_qkv + ((size_t)(j0 + ldr) * BATCH + b) * QKVN + EMB + h * HDIM;
            const float* vp = kp + EMB;
#pragma unroll
            for (int jj = 0; jj < 4; jj++) {
                int d0 = ldc * 16 + 4 * jj;
                float4 kv = *(const float4*)(kp + d0);
                uint4 uk = {f2tf32(kv.x), f2tf32(kv.y), f2tf32(kv.z), f2tf32(kv.w)};
                asm volatile("st.shared.v4.b32 [%0], {%1,%2,%3,%4};"
                    :: "r"(ksb + ldr * FSTR + d0 * 4),
                       "r"(uk.x), "r"(uk.y), "r"(uk.z), "r"(uk.w) : "memory");
                float4 vv = *(const float4*)(vp + d0);
                asm volatile("st.shared.b32 [%0], %1;" :: "r"(vtb + (d0+0) * FSTR + ldr * 4), "r"(f2tf32(vv.x)) : "memory");
                asm volatile("st.shared.b32 [%0], %1;" :: "r"(vtb + (d0+1) * FSTR + ldr * 4), "r"(f2tf32(vv.y)) : "memory");
                asm volatile("st.shared.b32 [%0], %1;" :: "r"(vtb + (d0+2) * FSTR + ldr * 4), "r"(f2tf32(vv.z)) : "memory");
                asm volatile("st.shared.b32 [%0], %1;" :: "r"(vtb + (d0+3) * FSTR + ldr * 4), "r"(f2tf32(vv.w)) : "memory");
            }
        }
        __syncthreads();

        // ---- S = Q @ K^T (16 x 64 per warp) ----
        float S[8][4];
#pragma unroll
        for (int nt = 0; nt < 8; nt++)
#pragma unroll
            for (int q = 0; q < 4; q++) S[nt][q] = 0.f;

#pragma unroll
        for (int ks = 0; ks < 8; ks++) {
            uint32_t qa[4];
            ldsm_x4(qa[0], qa[1], qa[2], qa[3], a_q + ks * 32);
            uint32_t b0[8], b1[8];
#pragma unroll
            for (int p = 0; p < 4; p++)
                ldsm_x4(b0[2*p], b0[2*p+1], b1[2*p], b1[2*p+1],
                        a_k + p * 16 * FSTR + ks * 32);
#pragma unroll
            for (int nt = 0; nt < 8; nt++)
                mma_tf32(S[nt], qa, b0[nt], b1[nt]);
        }

        // ---- mask + online softmax ----
        float rm0 = -1e30f, rm1 = -1e30f;
#pragma unroll
        for (int nt = 0; nt < 8; nt++) {
            uchar2 mk = *(const uchar2*)&mask[b * SEQ + j0 + nt * 8 + 2 * qd];
            if (mk.x) { S[nt][0] = -1e30f; S[nt][2] = -1e30f; }
            if (mk.y) { S[nt][1] = -1e30f; S[nt][3] = -1e30f; }
            rm0 = fmaxf(rm0, fmaxf(S[nt][0], S[nt][1]));
            rm1 = fmaxf(rm1, fmaxf(S[nt][2], S[nt][3]));
        }
#pragma unroll
        for (int off = 1; off <= 2; off <<= 1) {
            rm0 = fmaxf(rm0, __shfl_xor_sync(0xffffffffu, rm0, off));
            rm1 = fmaxf(rm1, __shfl_xor_sync(0xffffffffu, rm1, off));
        }
        float mn0 = fmaxf(m0, rm0), mn1 = fmaxf(m1, rm1);
        float cr0 = __expf(m0 - mn0), cr1 = __expf(m1 - mn1);
        float rs0 = 0.f, rs1 = 0.f;
#pragma unroll
        for (int nt = 0; nt < 8; nt++) {
            float p0 = __expf(S[nt][0] - mn0);
            float p1 = __expf(S[nt][1] - mn0);
            float p2 = __expf(S[nt][2] - mn1);
            float p3 = __expf(S[nt][3] - mn1);
            rs0 += p0 + p1; rs1 += p2 + p3;
            uint32_t ca = psb + (wr + g) * FSTR + (nt * 8 + 2 * qd) * 4;
            asm volatile("st.shared.v2.b32 [%0], {%1,%2};"
                :: "r"(ca), "r"(f2tf32(p0)), "r"(f2tf32(p1)) : "memory");
            asm volatile("st.shared.v2.b32 [%0], {%1,%2};"
                :: "r"(ca + 8 * FSTR), "r"(f2tf32(p2)), "r"(f2tf32(p3)) : "memory");
        }
#pragma unroll
        for (int off = 1; off <= 2; off <<= 1) {
            rs0 += __shfl_xor_sync(0xffffffffu, rs0, off);
            rs1 += __shfl_xor_sync(0xffffffffu, rs1, off);
        }
        l0 = l0 * cr0 + rs0;
        l1 = l1 * cr1 + rs1;
        m0 = mn0; m1 = mn1;
#pragma unroll
        for (int nt = 0; nt < 8; nt++) {
            O[nt][0] *= cr0; O[nt][1] *= cr0;
            O[nt][2] *= cr1; O[nt][3] *= cr1;
        }
        __syncwarp();

        // ---- O += P @ V ----
#pragma unroll
        for (int ks = 0; ks < 8; ks++) {
            uint32_t pa[4];
            ldsm_x4(pa[0], pa[1], pa[2], pa[3], a_p + ks * 32);
            uint32_t b0[8], b1[8];
#pragma unroll
            for (int p = 0; p < 4; p++)
                ldsm_x4(b0[2*p], b0[2*p+1], b1[2*p], b1[2*p+1],
                        a_v + p * 16 * FSTR + ks * 32);
#pragma unroll
            for (int nt = 0; nt < 8; nt++)
                mma_tf32(O[nt], pa, b0[nt], b1[nt]);
        }
        __syncthreads();
    }

    // ---- normalize + write out ----
    float inv0 = 1.f / l0, inv1 = 1.f / l1;
    const size_t row0 = ((size_t)(q0 + wr + g) * BATCH + b) * EMB + h * HDIM;
    const size_t row1 = ((size_t)(q0 + wr + g + 8) * BATCH + b) * EMB + h * HDIM;
#pragma unroll
    for (int nt = 0; nt < 8; nt++) {
        int col = nt * 8 + 2 * qd;
        float2 v0 = {O[nt][0] * inv0, O[nt][1] * inv0};
        *(float2*)&g_attn[row0 + col] = v0;
        float2 v1 = {O[nt][2] * inv1, O[nt][3] * inv1};
        *(float2*)&g_attn[row1 + col] = v1;
    }
}

// ---------------------------------------------------------------------------
// Launch
// ---------------------------------------------------------------------------
extern "C" void kernel_launch(void* const* d_in, const int* in_sizes, int n_in,
                              void* d_out, int out_size)
{
    const float*         x    = (const float*)d_in[0];
    const unsigned char* mask = (const unsigned char*)d_in[1];
    const float*         Win  = (const float*)d_in[2];
    const float*         bin  = (const float*)d_in[3];
    const float*         Wout = (const float*)d_in[4];
    const float*         bout = (const float*)d_in[5];
    float*               out  = (float*)d_out;

    float *qkv_ptr = nullptr, *attn_ptr = nullptr;
    cudaGetSymbolAddress((void**)&qkv_ptr, g_qkv);
    cudaGetSymbolAddress((void**)&attn_ptr, g_attn);

    cudaFuncSetAttribute(gemm_tc, cudaFuncAttributeMaxDynamicSharedMemorySize, GSMEM_TOTAL);
    cudaFuncSetAttribute(flash_tc, cudaFuncAttributeMaxDynamicSharedMemorySize, FATT_SMEM);

    // 1) QKV in-projection (mma.sync tf32)
    dim3 g1(QKVN / 128, MROWS / 128);
    gemm_tc<<<g1, 256, GSMEM_TOTAL>>>(x, Win, bin, qkv_ptr, MROWS, QKVN, EMB);

    // 2) flash attention (mma.sync tf32)
    dim3 g2(SEQ / 128, BATCH * NHEAD);
    flash_tc<<<g2, 256, FATT_SMEM>>>(mask);

    // 3) out-projection (mma.sync tf32)
    dim3 g3(EMB / 128, MROWS / 128);
    gemm_tc<<<g3, 256, GSMEM_TOTAL>>>(attn_ptr, Wout, bout, out, MROWS, EMB, EMB);
}

// round 6
// speedup vs baseline: 3.4155x; 1.2181x over previous
#include <cuda_runtime.h>
#include <cstdint>

// Problem constants: S=2048, B=2, E=1024, H=16, HD=64
#define SEQ   2048
#define BATCH 2
#define EMB   1024
#define NHEAD 16
#define HDIM  64
#define MROWS (SEQ*BATCH)     // 4096
#define QKVN  (3*EMB)         // 3072

__device__ float g_qkv[(size_t)MROWS * QKVN];    // 48 MB: [m][3E]
__device__ float g_attn[(size_t)MROWS * EMB];    // 16 MB: [m][E]
__device__ float g_kp[(size_t)BATCH * NHEAD * SEQ * HDIM];   // 16 MB: [bh][s][d] tf32
__device__ float g_vt[(size_t)BATCH * NHEAD * HDIM * SEQ];   // 16 MB: [bh][d][s] tf32

// ===========================================================================
// helpers
// ===========================================================================
__device__ __forceinline__ uint32_t smem_u32(const void* p) {
    uint32_t a;
    asm("{ .reg .u64 t; cvta.to.shared.u64 t, %1; cvt.u32.u64 %0, t; }" : "=r"(a) : "l"(p));
    return a;
}
__device__ __forceinline__ uint32_t f2tf32(float f) {
    uint32_t u;
    asm("cvt.rn.tf32.f32 %0, %1;" : "=r"(u) : "f"(f));
    return u;
}
__device__ __forceinline__ float rtf(float f) { return __uint_as_float(f2tf32(f)); }
__device__ __forceinline__ float ex2f(float x) {
    float y;
    asm("ex2.approx.f32 %0, %1;" : "=f"(y) : "f"(x));
    return y;
}
__device__ __forceinline__ void ldsm_x4(uint32_t& r0, uint32_t& r1, uint32_t& r2, uint32_t& r3, uint32_t addr) {
    asm volatile("ldmatrix.sync.aligned.m8n8.x4.shared.b16 {%0,%1,%2,%3}, [%4];"
        : "=r"(r0), "=r"(r1), "=r"(r2), "=r"(r3) : "r"(addr));
}
__device__ __forceinline__ void mma_tf32(float* c, const uint32_t* a, uint32_t b0, uint32_t b1) {
    asm volatile(
        "mma.sync.aligned.m16n8k8.row.col.f32.tf32.tf32.f32 "
        "{%0,%1,%2,%3}, {%4,%5,%6,%7}, {%8,%9}, {%0,%1,%2,%3};"
        : "+f"(c[0]), "+f"(c[1]), "+f"(c[2]), "+f"(c[3])
        : "r"(a[0]), "r"(a[1]), "r"(a[2]), "r"(a[3]), "r"(b0), "r"(b1));
}
#define SWZ128(b) ((b) ^ (((b) >> 3) & 0x70))
#define CPA(s, g)    asm volatile("cp.async.cg.shared.global [%0], [%1], 16;" :: "r"(s), "l"(g) : "memory")
#define CP_COMMIT()  asm volatile("cp.async.commit_group;" ::: "memory")
#define CP_WAIT1()   asm volatile("cp.async.wait_group 1;" ::: "memory")
#define CP_WAIT0()   asm volatile("cp.async.wait_group 0;" ::: "memory")

// ===========================================================================
// TF32 GEMM via mma.sync (unchanged from R5): C = A @ W^T + bias
// ===========================================================================
#define BK 32
#define TILEB (128 * 128)

__global__ __launch_bounds__(256)
void gemm_tc(const float* __restrict__ A, const float* __restrict__ W,
             const float* __restrict__ bias, float* __restrict__ C,
             int M, int N, int K)
{
    extern __shared__ char sm[];
    const uint32_t sb = smem_u32(sm);
    const int tid  = threadIdx.x;
    const int warp = tid >> 5;
    const int lane = tid & 31;
    const int wm = warp >> 2;
    const int wn = warp & 3;
    const int bm = blockIdx.y * 128, bn = blockIdx.x * 128;
    const int NK = K / BK;

    const int lrow = tid >> 3;
    const int lc4  = tid & 7;

    float c[4][4][4];
#pragma unroll
    for (int mi = 0; mi < 4; mi++)
#pragma unroll
        for (int ni = 0; ni < 4; ni++)
#pragma unroll
            for (int q = 0; q < 4; q++) c[mi][ni][q] = 0.f;

    float4 pa[4], pw[4];

    auto fetch = [&](int chunk) {
        const int k0 = chunk * BK + lc4 * 4;
#pragma unroll
        for (int it = 0; it < 4; it++) {
            int row = it * 32 + lrow;
            pa[it] = *(const float4*)&A[(size_t)(bm + row) * K + k0];
            pw[it] = *(const float4*)&W[(size_t)(bn + row) * K + k0];
        }
    };
    auto stash = [&](int buf) {
        const uint32_t ab = sb + buf * 2 * TILEB;
        const uint32_t wb = ab + TILEB;
#pragma unroll
        for (int it = 0; it < 4; it++) {
            int row = it * 32 + lrow;
            uint32_t bo = SWZ128((uint32_t)(row * 128 + lc4 * 16));
            uint4 ua = {f2tf32(pa[it].x), f2tf32(pa[it].y), f2tf32(pa[it].z), f2tf32(pa[it].w)};
            asm volatile("st.shared.v4.b32 [%0], {%1,%2,%3,%4};"
                :: "r"(ab + bo), "r"(ua.x), "r"(ua.y), "r"(ua.z), "r"(ua.w) : "memory");
            uint4 uw = {f2tf32(pw[it].x), f2tf32(pw[it].y), f2tf32(pw[it].z), f2tf32(pw[it].w)};
            asm volatile("st.shared.v4.b32 [%0], {%1,%2,%3,%4};"
                :: "r"(wb + bo), "r"(uw.x), "r"(uw.y), "r"(uw.z), "r"(uw.w) : "memory");
        }
    };

    const int lrow16 = lane & 15;
    const int lkhalf = (lane >> 4) * 16;

    auto compute = [&](int buf) {
        const uint32_t ab = sb + buf * 2 * TILEB;
        const uint32_t wb = ab + TILEB;
#pragma unroll
        for (int ks = 0; ks < 4; ks++) {
            const uint32_t kb = ks * 32 + lkhalf;
            uint32_t a[4][4];
#pragma unroll
            for (int mi = 0; mi < 4; mi++) {
                int row = wm * 64 + mi * 16 + lrow16;
                uint32_t addr = ab + SWZ128((uint32_t)(row * 128) + kb);
                ldsm_x4(a[mi][0], a[mi][1], a[mi][2], a[mi][3], addr);
            }
            uint32_t b0[4], b1[4];
#pragma unroll
            for (int p = 0; p < 2; p++) {
                int row = wn * 32 + p * 16 + lrow16;
                uint32_t addr = wb + SWZ128((uint32_t)(row * 128) + kb);
                ldsm_x4(b0[2*p], b0[2*p+1], b1[2*p], b1[2*p+1], addr);
            }
#pragma unroll
            for (int mi = 0; mi < 4; mi++)
#pragma unroll
                for (int ni = 0; ni < 4; ni++)
                    mma_tf32(c[mi][ni], a[mi], b0[ni], b1[ni]);
        }
    };

    fetch(0);
    stash(0);
    __syncthreads();
    for (int k = 0; k < NK; k++) {
        if (k + 1 < NK) fetch(k + 1);
        compute(k & 1);
        if (k + 1 < NK) {
            stash((k + 1) & 1);
            __syncthreads();
        }
    }

    const int g = lane >> 2, qd = lane & 3;
#pragma unroll
    for (int ni = 0; ni < 4; ni++) {
        int col = bn + wn * 32 + ni * 8 + qd * 2;
        float bz0 = bias[col], bz1 = bias[col + 1];
#pragma unroll
        for (int mi = 0; mi < 4; mi++) {
            int row = bm + wm * 64 + mi * 16 + g;
            float2 v0 = {c[mi][ni][0] + bz0, c[mi][ni][1] + bz1};
            *(float2*)&C[(size_t)row * N + col] = v0;
            float2 v1 = {c[mi][ni][2] + bz0, c[mi][ni][3] + bz1};
            *(float2*)&C[(size_t)(row + 8) * N + col] = v1;
        }
    }
}
#define GSMEM_TOTAL (4 * TILEB)

// ===========================================================================
// Repack: Q *= 0.125*log2e (tf32-round, in place); K -> g_kp[bh][s][d];
// V -> g_vt[bh][d][s] (transposed), both tf32-rounded.
// grid (SEQ/64, B*H), 256 threads.
// ===========================================================================
__global__ __launch_bounds__(256) void repack_k()
{
    __shared__ float vt[64][68];
    const int bh = blockIdx.y, b = bh >> 4, h = bh & 15;
    const int s0 = blockIdx.x * 64;
    const int t = threadIdx.x, r = t >> 2, c = t & 3;
    const float SC = 0.125f * 1.4426950408889634f;   // fold log2(e) for exp2 softmax

    float* qrow = g_qkv + ((size_t)(s0 + r) * BATCH + b) * QKVN + h * HDIM;
    float* kdst = g_kp + ((size_t)bh * SEQ + s0 + r) * HDIM;
#pragma unroll
    for (int i = 0; i < 4; i++) {
        int c4 = (c + 4 * i) * 4;
        float4 q = *(float4*)(qrow + c4);
        float4 qo = {rtf(q.x * SC), rtf(q.y * SC), rtf(q.z * SC), rtf(q.w * SC)};
        *(float4*)(qrow + c4) = qo;
        float4 k = *(float4*)(qrow + EMB + c4);
        float4 ko = {rtf(k.x), rtf(k.y), rtf(k.z), rtf(k.w)};
        *(float4*)(kdst + c4) = ko;
        float4 v = *(float4*)(qrow + 2 * EMB + c4);
        float4 vo = {rtf(v.x), rtf(v.y), rtf(v.z), rtf(v.w)};
        *(float4*)&vt[r][c4] = vo;
    }
    __syncthreads();
    // write transposed: rows = d, coalesced 256B chunks
    const int d = t >> 2, jc = t & 3;
    float* dst = g_vt + ((size_t)bh * HDIM + d) * SEQ + s0;
#pragma unroll
    for (int i = 0; i < 4; i++) {
        int j0 = (jc + 4 * i) * 4;
        float4 o = {vt[j0][d], vt[j0 + 1][d], vt[j0 + 2][d], vt[j0 + 3][d]};
        *(float4*)(dst + j0) = o;
    }
}

// ===========================================================================
// Flash attention v2: cp.async double-buffered K/V, shfl-based P transpose,
// exp2 softmax. 128 q-rows/CTA, 8 warps x 16 rows, BKV=64.
// smem: Q 34816 | K0 17408 | V0 17408 | K1 17408 | V1 17408 = 104448 (occ 2)
// ===========================================================================
#define FSTR 272
#define FATT_SMEM 104448

__global__ __launch_bounds__(256, 2)
void flash_tc(const unsigned char* __restrict__ mask)
{
    extern __shared__ char sm[];
    const uint32_t sb = smem_u32(sm);
    const uint32_t qsb = sb;

    const int tid  = threadIdx.x;
    const int warp = tid >> 5;
    const int lane = tid & 31;
    const int g  = lane >> 2;
    const int qd = lane & 3;
    const int lrow16 = lane & 15;
    const int lk16   = (lane >> 4) * 16;

    const int bh = blockIdx.y;
    const int b = bh >> 4, h = bh & 15;
    const int q0 = blockIdx.x * 128;
    const int wr = warp * 16;

    // ---- async load Q tile (pre-scaled, tf32-rounded in g_qkv) ----
    {
        const int r = tid >> 1;
        const char* qp = (const char*)(g_qkv + ((size_t)(q0 + r) * BATCH + b) * QKVN + h * HDIM)
                         + (tid & 1) * 128;
        uint32_t sq = qsb + r * FSTR + (tid & 1) * 128;
#pragma unroll
        for (int i = 0; i < 8; i++)
            CPA(sq + i * 16, qp + i * 16);
    }

    // K/V tile issue (16KB each, contiguous-row sources)
    auto issue_kv = [&](int j0, int buf) {
        const int r = tid >> 2, c0 = tid & 3;
        const uint32_t kb = sb + 34816 + buf * 34816;
        const uint32_t vb = kb + 17408;
        const char* gk = (const char*)(g_kp + ((size_t)bh * SEQ + j0 + r) * HDIM);
        const char* gv = (const char*)(g_vt + ((size_t)bh * HDIM + r) * SEQ + j0);
#pragma unroll
        for (int i = 0; i < 4; i++) {
            int cc = (c0 + 4 * i) * 16;
            CPA(kb + r * FSTR + cc, gk + cc);
            CPA(vb + r * FSTR + cc, gv + cc);
        }
    };

    issue_kv(0, 0);
    CP_COMMIT();   // group 0 = {Q, K0, V0}

    float O[8][4];
#pragma unroll
    for (int nt = 0; nt < 8; nt++)
#pragma unroll
        for (int q = 0; q < 4; q++) O[nt][q] = 0.f;
    float m0 = -1e30f, m1 = -1e30f, l0 = 0.f, l1 = 0.f;

    const uint32_t a_q = qsb + (wr + lrow16) * FSTR + lk16;

    for (int j = 0; j < SEQ / 64; j++) {
        const int buf = j & 1;
        if (j + 1 < SEQ / 64) {
            issue_kv((j + 1) * 64, buf ^ 1);
            CP_COMMIT();
            CP_WAIT1();
        } else {
            CP_WAIT0();
        }
        __syncthreads();

        const uint32_t kbase = sb + 34816 + buf * 34816;
        const uint32_t a_k = kbase + lrow16 * FSTR + lk16;
        const uint32_t a_v = kbase + 17408 + lrow16 * FSTR + lk16;

        // ---- S = Q @ K^T (16 x 64 per warp), log2-domain scores ----
        float S[8][4];
#pragma unroll
        for (int nt = 0; nt < 8; nt++)
#pragma unroll
            for (int q = 0; q < 4; q++) S[nt][q] = 0.f;

#pragma unroll
        for (int ks = 0; ks < 8; ks++) {
            uint32_t qa[4];
            ldsm_x4(qa[0], qa[1], qa[2], qa[3], a_q + ks * 32);
            uint32_t b0[8], b1[8];
#pragma unroll
            for (int p = 0; p < 4; p++)
                ldsm_x4(b0[2*p], b0[2*p+1], b1[2*p], b1[2*p+1],
                        a_k + p * 16 * FSTR + ks * 32);
#pragma unroll
            for (int nt = 0; nt < 8; nt++)
                mma_tf32(S[nt], qa, b0[nt], b1[nt]);
        }

        // ---- mask + online softmax (base 2) ----
        float rm0 = -1e30f, rm1 = -1e30f;
#pragma unroll
        for (int nt = 0; nt < 8; nt++) {
            uchar2 mk = *(const uchar2*)&mask[b * SEQ + j * 64 + nt * 8 + 2 * qd];
            if (mk.x) { S[nt][0] = -1e30f; S[nt][2] = -1e30f; }
            if (mk.y) { S[nt][1] = -1e30f; S[nt][3] = -1e30f; }
            rm0 = fmaxf(rm0, fmaxf(S[nt][0], S[nt][1]));
            rm1 = fmaxf(rm1, fmaxf(S[nt][2], S[nt][3]));
        }
#pragma unroll
        for (int off = 1; off <= 2; off <<= 1) {
            rm0 = fmaxf(rm0, __shfl_xor_sync(0xffffffffu, rm0, off));
            rm1 = fmaxf(rm1, __shfl_xor_sync(0xffffffffu, rm1, off));
        }
        const float mn0 = fmaxf(m0, rm0), mn1 = fmaxf(m1, rm1);
        const float cr0 = ex2f(m0 - mn0), cr1 = ex2f(m1 - mn1);
        float rs0 = 0.f, rs1 = 0.f;
#pragma unroll
        for (int nt = 0; nt < 8; nt++) {
            float p0 = ex2f(S[nt][0] - mn0);
            float p1 = ex2f(S[nt][1] - mn0);
            float p2 = ex2f(S[nt][2] - mn1);
            float p3 = ex2f(S[nt][3] - mn1);
            rs0 += p0 + p1; rs1 += p2 + p3;
            // store tf32 bits in place (fp32 with low mantissa zeroed)
            S[nt][0] = __uint_as_float(f2tf32(p0));
            S[nt][1] = __uint_as_float(f2tf32(p1));
            S[nt][2] = __uint_as_float(f2tf32(p2));
            S[nt][3] = __uint_as_float(f2tf32(p3));
        }
#pragma unroll
        for (int off = 1; off <= 2; off <<= 1) {
            rs0 += __shfl_xor_sync(0xffffffffu, rs0, off);
            rs1 += __shfl_xor_sync(0xffffffffu, rs1, off);
        }
        l0 = l0 * cr0 + rs0;
        l1 = l1 * cr1 + rs1;
        m0 = mn0; m1 = mn1;
#pragma unroll
        for (int nt = 0; nt < 8; nt++) {
            O[nt][0] *= cr0; O[nt][1] *= cr0;
            O[nt][2] *= cr1; O[nt][3] *= cr1;
        }

        // ---- O += P @ V : P a-frags via register shuffles ----
        const int L0 = 4 * g + (qd >> 1);
        const int L2 = L0 + 2;
        const bool sel = qd & 1;
#pragma unroll
        for (int ks = 0; ks < 8; ks++) {
            float s00 = __shfl_sync(0xffffffffu, S[ks][0], L0);
            float s01 = __shfl_sync(0xffffffffu, S[ks][1], L0);
            float s02 = __shfl_sync(0xffffffffu, S[ks][2], L0);
            float s03 = __shfl_sync(0xffffffffu, S[ks][3], L0);
            float s20 = __shfl_sync(0xffffffffu, S[ks][0], L2);
            float s21 = __shfl_sync(0xffffffffu, S[ks][1], L2);
            float s22 = __shfl_sync(0xffffffffu, S[ks][2], L2);
            float s23 = __shfl_sync(0xffffffffu, S[ks][3], L2);
            uint32_t pa[4];
            pa[0] = __float_as_uint(sel ? s01 : s00);  // P[g][8ks+qd]
            pa[1] = __float_as_uint(sel ? s03 : s02);  // P[g+8][8ks+qd]
            pa[2] = __float_as_uint(sel ? s21 : s20);  // P[g][8ks+4+qd]
            pa[3] = __float_as_uint(sel ? s23 : s22);  // P[g+8][8ks+4+qd]
            uint32_t b0[8], b1[8];
#pragma unroll
            for (int p = 0; p < 4; p++)
                ldsm_x4(b0[2*p], b0[2*p+1], b1[2*p], b1[2*p+1],
                        a_v + p * 16 * FSTR + ks * 32);
#pragma unroll
            for (int nt = 0; nt < 8; nt++)
                mma_tf32(O[nt], pa, b0[nt], b1[nt]);
        }
        __syncthreads();
    }

    // ---- normalize + write out ----
    const float inv0 = 1.f / l0, inv1 = 1.f / l1;
    const size_t row0 = ((size_t)(q0 + wr + g) * BATCH + b) * EMB + h * HDIM;
    const size_t row1 = ((size_t)(q0 + wr + g + 8) * BATCH + b) * EMB + h * HDIM;
#pragma unroll
    for (int nt = 0; nt < 8; nt++) {
        int col = nt * 8 + 2 * qd;
        float2 v0 = {O[nt][0] * inv0, O[nt][1] * inv0};
        *(float2*)&g_attn[row0 + col] = v0;
        float2 v1 = {O[nt][2] * inv1, O[nt][3] * inv1};
        *(float2*)&g_attn[row1 + col] = v1;
    }
}

// ---------------------------------------------------------------------------
// Launch
// ---------------------------------------------------------------------------
extern "C" void kernel_launch(void* const* d_in, const int* in_sizes, int n_in,
                              void* d_out, int out_size)
{
    const float*         x    = (const float*)d_in[0];
    const unsigned char* mask = (const unsigned char*)d_in[1];
    const float*         Win  = (const float*)d_in[2];
    const float*         bin  = (const float*)d_in[3];
    const float*         Wout = (const float*)d_in[4];
    const float*         bout = (const float*)d_in[5];
    float*               out  = (float*)d_out;

    float *qkv_ptr = nullptr, *attn_ptr = nullptr;
    cudaGetSymbolAddress((void**)&qkv_ptr, g_qkv);
    cudaGetSymbolAddress((void**)&attn_ptr, g_attn);

    cudaFuncSetAttribute(gemm_tc, cudaFuncAttributeMaxDynamicSharedMemorySize, GSMEM_TOTAL);
    cudaFuncSetAttribute(flash_tc, cudaFuncAttributeMaxDynamicSharedMemorySize, FATT_SMEM);

    // 1) QKV in-projection (mma.sync tf32)
    dim3 g1(QKVN / 128, MROWS / 128);
    gemm_tc<<<g1, 256, GSMEM_TOTAL>>>(x, Win, bin, qkv_ptr, MROWS, QKVN, EMB);

    // 2) repack: Q scale+round in place, K -> g_kp, V^T -> g_vt
    dim3 gr(SEQ / 64, BATCH * NHEAD);
    repack_k<<<gr, 256>>>();

    // 3) flash attention (cp.async pipelined, mma.sync tf32)
    dim3 g2(SEQ / 128, BATCH * NHEAD);
    flash_tc<<<g2, 256, FATT_SMEM>>>(mask);

    // 4) out-projection (mma.sync tf32)
    dim3 g3(EMB / 128, MROWS / 128);
    gemm_tc<<<g3, 256, GSMEM_TOTAL>>>(attn_ptr, Wout, bout, out, MROWS, EMB, EMB);
}

// round 7
// speedup vs baseline: 3.4650x; 1.0145x over previous
#include <cuda_runtime.h>
#include <cstdint>

// Problem constants: S=2048, B=2, E=1024, H=16, HD=64
#define SEQ   2048
#define BATCH 2
#define EMB   1024
#define NHEAD 16
#define HDIM  64
#define MROWS (SEQ*BATCH)     // 4096
#define QKVN  (3*EMB)         // 3072

__device__ float g_qkv[(size_t)MROWS * QKVN];    // 48 MB
__device__ float g_attn[(size_t)MROWS * EMB];    // 16 MB (tf32-rounded by flash)
__device__ float g_kp[(size_t)BATCH * NHEAD * SEQ * HDIM];   // 16 MB tf32
__device__ float g_vt[(size_t)BATCH * NHEAD * HDIM * SEQ];   // 16 MB tf32
__device__ float g_xr[(size_t)MROWS * EMB];      // 16 MB: x tf32-rounded
__device__ float g_wir[(size_t)QKVN * EMB];      // 12 MB: Win tf32-rounded
__device__ float g_wor[(size_t)EMB * EMB];       //  4 MB: Wout tf32-rounded

// ===========================================================================
// helpers
// ===========================================================================
__device__ __forceinline__ uint32_t smem_u32(const void* p) {
    uint32_t a;
    asm("{ .reg .u64 t; cvta.to.shared.u64 t, %1; cvt.u32.u64 %0, t; }" : "=r"(a) : "l"(p));
    return a;
}
__device__ __forceinline__ uint32_t f2tf32(float f) {
    uint32_t u;
    asm("cvt.rn.tf32.f32 %0, %1;" : "=r"(u) : "f"(f));
    return u;
}
__device__ __forceinline__ float rtf(float f) { return __uint_as_float(f2tf32(f)); }
__device__ __forceinline__ float ex2f(float x) {
    float y;
    asm("ex2.approx.f32 %0, %1;" : "=f"(y) : "f"(x));
    return y;
}
__device__ __forceinline__ void ldsm_x4(uint32_t& r0, uint32_t& r1, uint32_t& r2, uint32_t& r3, uint32_t addr) {
    asm volatile("ldmatrix.sync.aligned.m8n8.x4.shared.b16 {%0,%1,%2,%3}, [%4];"
        : "=r"(r0), "=r"(r1), "=r"(r2), "=r"(r3) : "r"(addr));
}
__device__ __forceinline__ void mma_tf32(float* c, const uint32_t* a, uint32_t b0, uint32_t b1) {
    asm volatile(
        "mma.sync.aligned.m16n8k8.row.col.f32.tf32.tf32.f32 "
        "{%0,%1,%2,%3}, {%4,%5,%6,%7}, {%8,%9}, {%0,%1,%2,%3};"
        : "+f"(c[0]), "+f"(c[1]), "+f"(c[2]), "+f"(c[3])
        : "r"(a[0]), "r"(a[1]), "r"(a[2]), "r"(a[3]), "r"(b0), "r"(b1));
}
#define SWZ128(b) ((b) ^ (((b) >> 3) & 0x70))
#define CPA(s, g)    asm volatile("cp.async.cg.shared.global [%0], [%1], 16;" :: "r"(s), "l"(g) : "memory")
#define CP_COMMIT()  asm volatile("cp.async.commit_group;" ::: "memory")
#define CP_WAIT1()   asm volatile("cp.async.wait_group 1;" ::: "memory")
#define CP_WAIT0()   asm volatile("cp.async.wait_group 0;" ::: "memory")

// ===========================================================================
// round3: one-time tf32 rounding of x, Win, Wout into scratch
// ===========================================================================
__global__ __launch_bounds__(256) void round3(
    const float* __restrict__ x, const float* __restrict__ Win,
    const float* __restrict__ Wout)
{
    const size_t NX = (size_t)MROWS * EMB / 4;
    const size_t NI = (size_t)QKVN * EMB / 4;
    const size_t NO = (size_t)EMB * EMB / 4;
    const size_t stride = (size_t)gridDim.x * blockDim.x;
    size_t i0 = (size_t)blockIdx.x * blockDim.x + threadIdx.x;
    for (size_t i = i0; i < NX; i += stride) {
        float4 v = ((const float4*)x)[i];
        ((float4*)g_xr)[i] = {rtf(v.x), rtf(v.y), rtf(v.z), rtf(v.w)};
    }
    for (size_t i = i0; i < NI; i += stride) {
        float4 v = ((const float4*)Win)[i];
        ((float4*)g_wir)[i] = {rtf(v.x), rtf(v.y), rtf(v.z), rtf(v.w)};
    }
    for (size_t i = i0; i < NO; i += stride) {
        float4 v = ((const float4*)Wout)[i];
        ((float4*)g_wor)[i] = {rtf(v.x), rtf(v.y), rtf(v.z), rtf(v.w)};
    }
}

// ===========================================================================
// TF32 GEMM v2: cp.async 3-stage pipeline. Inputs MUST be tf32-rounded fp32.
// C[M,N] = A[M,K] @ W[N,K]^T + bias[N]. 128x128x32 tile, 256 thr, 8 warps.
// smem: 3 x (A 16KB + W 16KB) = 96KB.
// ===========================================================================
#define BK 32
#define TILEB (128 * 128)
#define GSMEM_TOTAL (6 * TILEB)

__global__ __launch_bounds__(256)
void gemm_tc(const float* __restrict__ A, const float* __restrict__ W,
             const float* __restrict__ bias, float* __restrict__ C,
             int M, int N, int K)
{
    extern __shared__ char sm[];
    const uint32_t sb = smem_u32(sm);
    const int tid  = threadIdx.x;
    const int warp = tid >> 5;
    const int lane = tid & 31;
    const int wm = warp >> 2;
    const int wn = warp & 3;
    const int bm = blockIdx.y * 128, bn = blockIdx.x * 128;
    const int NK = K / BK;

    float c[4][4][4];
#pragma unroll
    for (int mi = 0; mi < 4; mi++)
#pragma unroll
        for (int ni = 0; ni < 4; ni++)
#pragma unroll
            for (int q = 0; q < 4; q++) c[mi][ni][q] = 0.f;

    // cp.async tile issue: 1024 16B segments per tile, 4 per thread per tile
    const int irow = tid >> 1;              // paired mapping: 2 threads/row...
    auto issue = [&](int chunk, int buf) {
        const uint32_t ab = sb + buf * 2 * TILEB;
        const uint32_t wb = ab + TILEB;
        const int k0 = chunk * BK;
#pragma unroll
        for (int i = 0; i < 4; i++) {
            int idx = i * 256 + tid;
            int row = idx >> 3, c4 = idx & 7;
            uint32_t bo = SWZ128((uint32_t)(row * 128 + c4 * 16));
            CPA(ab + bo, &A[(size_t)(bm + row) * K + k0 + c4 * 4]);
            CPA(wb + bo, &W[(size_t)(bn + row) * K + k0 + c4 * 4]);
        }
    };

    const int lrow16 = lane & 15;
    const int lkhalf = (lane >> 4) * 16;

    auto compute = [&](int buf) {
        const uint32_t ab = sb + buf * 2 * TILEB;
        const uint32_t wb = ab + TILEB;
#pragma unroll
        for (int ks = 0; ks < 4; ks++) {
            const uint32_t kb = ks * 32 + lkhalf;
            uint32_t a[4][4];
#pragma unroll
            for (int mi = 0; mi < 4; mi++) {
                int row = wm * 64 + mi * 16 + lrow16;
                uint32_t addr = ab + SWZ128((uint32_t)(row * 128) + kb);
                ldsm_x4(a[mi][0], a[mi][1], a[mi][2], a[mi][3], addr);
            }
            uint32_t b0[4], b1[4];
#pragma unroll
            for (int p = 0; p < 2; p++) {
                int row = wn * 32 + p * 16 + lrow16;
                uint32_t addr = wb + SWZ128((uint32_t)(row * 128) + kb);
                ldsm_x4(b0[2*p], b0[2*p+1], b1[2*p], b1[2*p+1], addr);
            }
#pragma unroll
            for (int mi = 0; mi < 4; mi++)
#pragma unroll
                for (int ni = 0; ni < 4; ni++)
                    mma_tf32(c[mi][ni], a[mi], b0[ni], b1[ni]);
        }
    };

    // 3-stage pipeline
    issue(0, 0); CP_COMMIT();
    issue(1, 1); CP_COMMIT();
    for (int k = 0; k < NK; k++) {
        CP_WAIT1();                  // chunk k resident (only newest may pend)
        __syncthreads();             // visibility + buffer (k+2)%3 free
        if (k + 2 < NK) { issue(k + 2, (k + 2) % 3); CP_COMMIT(); }
        compute(k % 3);
    }

    const int g = lane >> 2, qd = lane & 3;
#pragma unroll
    for (int ni = 0; ni < 4; ni++) {
        int col = bn + wn * 32 + ni * 8 + qd * 2;
        float bz0 = bias[col], bz1 = bias[col + 1];
#pragma unroll
        for (int mi = 0; mi < 4; mi++) {
            int row = bm + wm * 64 + mi * 16 + g;
            float2 v0 = {c[mi][ni][0] + bz0, c[mi][ni][1] + bz1};
            *(float2*)&C[(size_t)row * N + col] = v0;
            float2 v1 = {c[mi][ni][2] + bz0, c[mi][ni][3] + bz1};
            *(float2*)&C[(size_t)(row + 8) * N + col] = v1;
        }
    }
}

// ===========================================================================
// Repack: Q *= 0.125*log2e (tf32-round, in place); K -> g_kp[bh][s][d];
// V -> g_vt[bh][d][s] (transposed), both tf32-rounded.
// ===========================================================================
__global__ __launch_bounds__(256) void repack_k()
{
    __shared__ float vt[64][68];
    const int bh = blockIdx.y, b = bh >> 4, h = bh & 15;
    const int s0 = blockIdx.x * 64;
    const int t = threadIdx.x, r = t >> 2, c = t & 3;
    const float SC = 0.125f * 1.4426950408889634f;

    float* qrow = g_qkv + ((size_t)(s0 + r) * BATCH + b) * QKVN + h * HDIM;
    float* kdst = g_kp + ((size_t)bh * SEQ + s0 + r) * HDIM;
#pragma unroll
    for (int i = 0; i < 4; i++) {
        int c4 = (c + 4 * i) * 4;
        float4 q = *(float4*)(qrow + c4);
        float4 qo = {rtf(q.x * SC), rtf(q.y * SC), rtf(q.z * SC), rtf(q.w * SC)};
        *(float4*)(qrow + c4) = qo;
        float4 k = *(float4*)(qrow + EMB + c4);
        float4 ko = {rtf(k.x), rtf(k.y), rtf(k.z), rtf(k.w)};
        *(float4*)(kdst + c4) = ko;
        float4 v = *(float4*)(qrow + 2 * EMB + c4);
        float4 vo = {rtf(v.x), rtf(v.y), rtf(v.z), rtf(v.w)};
        *(float4*)&vt[r][c4] = vo;
    }
    __syncthreads();
    const int d = t >> 2, jc = t & 3;
    float* dst = g_vt + ((size_t)bh * HDIM + d) * SEQ + s0;
#pragma unroll
    for (int i = 0; i < 4; i++) {
        int j0 = (jc + 4 * i) * 4;
        float4 o = {vt[j0][d], vt[j0 + 1][d], vt[j0 + 2][d], vt[j0 + 3][d]};
        *(float4*)(dst + j0) = o;
    }
}

// ===========================================================================
// Flash attention (R6 structure, output tf32-rounded)
// ===========================================================================
#define FSTR 272
#define FATT_SMEM 104448

__global__ __launch_bounds__(256, 2)
void flash_tc(const unsigned char* __restrict__ mask)
{
    extern __shared__ char sm[];
    const uint32_t sb = smem_u32(sm);
    const uint32_t qsb = sb;

    const int tid  = threadIdx.x;
    const int warp = tid >> 5;
    const int lane = tid & 31;
    const int g  = lane >> 2;
    const int qd = lane & 3;
    const int lrow16 = lane & 15;
    const int lk16   = (lane >> 4) * 16;

    const int bh = blockIdx.y;
    const int b = bh >> 4, h = bh & 15;
    const int q0 = blockIdx.x * 128;
    const int wr = warp * 16;

    {
        const int r = tid >> 1;
        const char* qp = (const char*)(g_qkv + ((size_t)(q0 + r) * BATCH + b) * QKVN + h * HDIM)
                         + (tid & 1) * 128;
        uint32_t sq = qsb + r * FSTR + (tid & 1) * 128;
#pragma unroll
        for (int i = 0; i < 8; i++)
            CPA(sq + i * 16, qp + i * 16);
    }

    auto issue_kv = [&](int j0, int buf) {
        const int r = tid >> 2, c0 = tid & 3;
        const uint32_t kb = sb + 34816 + buf * 34816;
        const uint32_t vb = kb + 17408;
        const char* gk = (const char*)(g_kp + ((size_t)bh * SEQ + j0 + r) * HDIM);
        const char* gv = (const char*)(g_vt + ((size_t)bh * HDIM + r) * SEQ + j0);
#pragma unroll
        for (int i = 0; i < 4; i++) {
            int cc = (c0 + 4 * i) * 16;
            CPA(kb + r * FSTR + cc, gk + cc);
            CPA(vb + r * FSTR + cc, gv + cc);
        }
    };

    issue_kv(0, 0);
    CP_COMMIT();

    float O[8][4];
#pragma unroll
    for (int nt = 0; nt < 8; nt++)
#pragma unroll
        for (int q = 0; q < 4; q++) O[nt][q] = 0.f;
    float m0 = -1e30f, m1 = -1e30f, l0 = 0.f, l1 = 0.f;

    const uint32_t a_q = qsb + (wr + lrow16) * FSTR + lk16;

    for (int j = 0; j < SEQ / 64; j++) {
        const int buf = j & 1;
        if (j + 1 < SEQ / 64) {
            issue_kv((j + 1) * 64, buf ^ 1);
            CP_COMMIT();
            CP_WAIT1();
        } else {
            CP_WAIT0();
        }
        __syncthreads();

        const uint32_t kbase = sb + 34816 + buf * 34816;
        const uint32_t a_k = kbase + lrow16 * FSTR + lk16;
        const uint32_t a_v = kbase + 17408 + lrow16 * FSTR + lk16;

        float S[8][4];
#pragma unroll
        for (int nt = 0; nt < 8; nt++)
#pragma unroll
            for (int q = 0; q < 4; q++) S[nt][q] = 0.f;

#pragma unroll
        for (int ks = 0; ks < 8; ks++) {
            uint32_t qa[4];
            ldsm_x4(qa[0], qa[1], qa[2], qa[3], a_q + ks * 32);
            uint32_t b0[8], b1[8];
#pragma unroll
            for (int p = 0; p < 4; p++)
                ldsm_x4(b0[2*p], b0[2*p+1], b1[2*p], b1[2*p+1],
                        a_k + p * 16 * FSTR + ks * 32);
#pragma unroll
            for (int nt = 0; nt < 8; nt++)
                mma_tf32(S[nt], qa, b0[nt], b1[nt]);
        }

        float rm0 = -1e30f, rm1 = -1e30f;
#pragma unroll
        for (int nt = 0; nt < 8; nt++) {
            uchar2 mk = *(const uchar2*)&mask[b * SEQ + j * 64 + nt * 8 + 2 * qd];
            if (mk.x) { S[nt][0] = -1e30f; S[nt][2] = -1e30f; }
            if (mk.y) { S[nt][1] = -1e30f; S[nt][3] = -1e30f; }
            rm0 = fmaxf(rm0, fmaxf(S[nt][0], S[nt][1]));
            rm1 = fmaxf(rm1, fmaxf(S[nt][2], S[nt][3]));
        }
#pragma unroll
        for (int off = 1; off <= 2; off <<= 1) {
            rm0 = fmaxf(rm0, __shfl_xor_sync(0xffffffffu, rm0, off));
            rm1 = fmaxf(rm1, __shfl_xor_sync(0xffffffffu, rm1, off));
        }
        const float mn0 = fmaxf(m0, rm0), mn1 = fmaxf(m1, rm1);
        const float cr0 = ex2f(m0 - mn0), cr1 = ex2f(m1 - mn1);
        float rs0 = 0.f, rs1 = 0.f;
#pragma unroll
        for (int nt = 0; nt < 8; nt++) {
            float p0 = ex2f(S[nt][0] - mn0);
            float p1 = ex2f(S[nt][1] - mn0);
            float p2 = ex2f(S[nt][2] - mn1);
            float p3 = ex2f(S[nt][3] - mn1);
            rs0 += p0 + p1; rs1 += p2 + p3;
            S[nt][0] = __uint_as_float(f2tf32(p0));
            S[nt][1] = __uint_as_float(f2tf32(p1));
            S[nt][2] = __uint_as_float(f2tf32(p2));
            S[nt][3] = __uint_as_float(f2tf32(p3));
        }
#pragma unroll
        for (int off = 1; off <= 2; off <<= 1) {
            rs0 += __shfl_xor_sync(0xffffffffu, rs0, off);
            rs1 += __shfl_xor_sync(0xffffffffu, rs1, off);
        }
        l0 = l0 * cr0 + rs0;
        l1 = l1 * cr1 + rs1;
        m0 = mn0; m1 = mn1;
#pragma unroll
        for (int nt = 0; nt < 8; nt++) {
            O[nt][0] *= cr0; O[nt][1] *= cr0;
            O[nt][2] *= cr1; O[nt][3] *= cr1;
        }

        const int L0 = 4 * g + (qd >> 1);
        const int L2 = L0 + 2;
        const bool sel = qd & 1;
#pragma unroll
        for (int ks = 0; ks < 8; ks++) {
            float s00 = __shfl_sync(0xffffffffu, S[ks][0], L0);
            float s01 = __shfl_sync(0xffffffffu, S[ks][1], L0);
            float s02 = __shfl_sync(0xffffffffu, S[ks][2], L0);
            float s03 = __shfl_sync(0xffffffffu, S[ks][3], L0);
            float s20 = __shfl_sync(0xffffffffu, S[ks][0], L2);
            float s21 = __shfl_sync(0xffffffffu, S[ks][1], L2);
            float s22 = __shfl_sync(0xffffffffu, S[ks][2], L2);
            float s23 = __shfl_sync(0xffffffffu, S[ks][3], L2);
            uint32_t pa[4];
            pa[0] = __float_as_uint(sel ? s01 : s00);
            pa[1] = __float_as_uint(sel ? s03 : s02);
            pa[2] = __float_as_uint(sel ? s21 : s20);
            pa[3] = __float_as_uint(sel ? s23 : s22);
            uint32_t b0[8], b1[8];
#pragma unroll
            for (int p = 0; p < 4; p++)
                ldsm_x4(b0[2*p], b0[2*p+1], b1[2*p], b1[2*p+1],
                        a_v + p * 16 * FSTR + ks * 32);
#pragma unroll
            for (int nt = 0; nt < 8; nt++)
                mma_tf32(O[nt], pa, b0[nt], b1[nt]);
        }
        __syncthreads();
    }

    // ---- normalize + write out (tf32-rounded for gemm2 direct consumption) ----
    const float inv0 = 1.f / l0, inv1 = 1.f / l1;
    const size_t row0 = ((size_t)(q0 + wr + g) * BATCH + b) * EMB + h * HDIM;
    const size_t row1 = ((size_t)(q0 + wr + g + 8) * BATCH + b) * EMB + h * HDIM;
#pragma unroll
    for (int nt = 0; nt < 8; nt++) {
        int col = nt * 8 + 2 * qd;
        float2 v0 = {rtf(O[nt][0] * inv0), rtf(O[nt][1] * inv0)};
        *(float2*)&g_attn[row0 + col] = v0;
        float2 v1 = {rtf(O[nt][2] * inv1), rtf(O[nt][3] * inv1)};
        *(float2*)&g_attn[row1 + col] = v1;
    }
}

// ---------------------------------------------------------------------------
// Launch
// ---------------------------------------------------------------------------
extern "C" void kernel_launch(void* const* d_in, const int* in_sizes, int n_in,
                              void* d_out, int out_size)
{
    const float*         x    = (const float*)d_in[0];
    const unsigned char* mask = (const unsigned char*)d_in[1];
    const float*         Win  = (const float*)d_in[2];
    const float*         bin  = (const float*)d_in[3];
    const float*         Wout = (const float*)d_in[4];
    const float*         bout = (const float*)d_in[5];
    float*               out  = (float*)d_out;

    float *qkv_ptr = nullptr, *attn_ptr = nullptr, *xr = nullptr, *wir = nullptr, *wor = nullptr;
    cudaGetSymbolAddress((void**)&qkv_ptr, g_qkv);
    cudaGetSymbolAddress((void**)&attn_ptr, g_attn);
    cudaGetSymbolAddress((void**)&xr, g_xr);
    cudaGetSymbolAddress((void**)&wir, g_wir);
    cudaGetSymbolAddress((void**)&wor, g_wor);

    cudaFuncSetAttribute(gemm_tc, cudaFuncAttributeMaxDynamicSharedMemorySize, GSMEM_TOTAL);
    cudaFuncSetAttribute(flash_tc, cudaFuncAttributeMaxDynamicSharedMemorySize, FATT_SMEM);

    // 0) one-time tf32 rounding of inputs
    round3<<<1184, 256>>>(x, Win, Wout);

    // 1) QKV in-projection (cp.async-pipelined tf32 mma)
    dim3 g1(QKVN / 128, MROWS / 128);
    gemm_tc<<<g1, 256, GSMEM_TOTAL>>>(xr, wir, bin, qkv_ptr, MROWS, QKVN, EMB);

    // 2) repack: Q scale+round in place, K -> g_kp, V^T -> g_vt
    dim3 gr(SEQ / 64, BATCH * NHEAD);
    repack_k<<<gr, 256>>>();

    // 3) flash attention
    dim3 g2(SEQ / 128, BATCH * NHEAD);
    flash_tc<<<g2, 256, FATT_SMEM>>>(mask);

    // 4) out-projection
    dim3 g3(EMB / 128, MROWS / 128);
    gemm_tc<<<g3, 256, GSMEM_TOTAL>>>(attn_ptr, wor, bout, out, MROWS, EMB, EMB);
}